// round 11
// baseline (speedup 1.0000x reference)
#include <cuda_runtime.h>
#include <math.h>

#define EPSf 1e-6f
#define NT 256
#define STR 108   // float4-aligned row stride; 27*tx mod 8 permutation -> conflict-free

// ---- shared memory layout (float offsets) — 26,866 floats = 105 KB ----
#define S1O   0        // s1R[ii*108+d]  local 50 rows (5400)
#define S2O   5400     // s2R[j*108+d]   100 rows (10800)
#define CMO   16200    // cm[ii*108+j] (5400) — reused as att[ii*108+d] after phase 5
#define WMO   21600    // w_maxpool^2 [p*100+d] (1000)
#define R1WO  22600    // 1/n1w [ii*10+p] (500)
#define R2WO  23100    // 1/n2w [j*10+p] (1000)
#define R1O   24100    // 1/||s1_ii|| (50)
#define R2O   24150    // 1/||s2_j|| (100)
#define RSO   24250    // rowsum per ii (50)
#define JMO   24300    // argmax j per ii (int) (50)
#define R2FO  24350    // full n2 per p (16)
#define MPO   24366    // maxpool scratch 2 p-slots [slot*1250 + ii*25 + tx] (2500)
#define SMEM_FLOATS 26866

__device__ __forceinline__ float invs(float x) {
    return 1.0f / sqrtf(fmaxf(x, EPSf));
}

__device__ __forceinline__ float2 ffma2(float2 a, float2 b, float2 c) {
    unsigned long long ua = *reinterpret_cast<unsigned long long*>(&a);
    unsigned long long ub = *reinterpret_cast<unsigned long long*>(&b);
    unsigned long long uc = *reinterpret_cast<unsigned long long*>(&c);
    unsigned long long ud;
    asm("fma.rn.f32x2 %0, %1, %2, %3;" : "=l"(ud) : "l"(ua), "l"(ub), "l"(uc));
    return *reinterpret_cast<float2*>(&ud);
}
__device__ __forceinline__ float2 fmul2(float2 a, float2 b) {
    unsigned long long ua = *reinterpret_cast<unsigned long long*>(&a);
    unsigned long long ub = *reinterpret_cast<unsigned long long*>(&b);
    unsigned long long ud;
    asm("mul.rn.f32x2 %0, %1, %2;" : "=l"(ud) : "l"(ua), "l"(ub));
    return *reinterpret_cast<float2*>(&ud);
}

__global__ __launch_bounds__(NT, 2) void matching_kernel(
    const float* __restrict__ s1g, const float* __restrict__ s2g,
    const float* __restrict__ w1, const float* __restrict__ w2,
    const float* __restrict__ w3, const float* __restrict__ w4,
    const float* __restrict__ w5, const float* __restrict__ w6,
    const float* __restrict__ w7, const float* __restrict__ w8,
    float* __restrict__ out)
{
    extern __shared__ float sm[];
    const int b   = blockIdx.x;        // batch 0..255
    const int dir = blockIdx.y;        // 0=fwd, 1=bwd
    const int ib  = blockIdx.z * 50;   // i half: global rows [ib, ib+50)
    const int tid = threadIdx.x;
    const int dOff = dir * 100;

    float* s1R = sm + S1O;
    float* s2R = sm + S2O;
    float* cm  = sm + CMO;             // cm during phases 2-5, att afterwards

    const float* wf = dir ? w2 : w1;
    const float* wm = dir ? w4 : w3;
    const float* we = dir ? w6 : w5;
    const float* ws = dir ? w8 : w7;

    // ================= phase 0: wm^2 + s1 half + s2 full into smem ==========
    for (int e = tid; e < 1000; e += NT) {
        float a = wm[e]; sm[WMO + e] = a * a;
    }
    for (int e = tid; e < 5000; e += NT) {
        int ii = e / 100, d = e - ii * 100;
        s1R[ii * STR + d] = s1g[((size_t)(ib + ii) * 256 + b) * 200 + dOff + d];
    }
    for (int e = tid; e < 10000; e += NT) {
        int j = e / 100, d = e - j * 100;
        s2R[j * STR + d] = s2g[((size_t)j * 256 + b) * 200 + dOff + d];
    }
    __syncthreads();

    // ================= phase 1: norms (parallel sub-jobs) ===================
    if (tid < 50) {                          // 1/||s1_ii||
        float2 a = make_float2(0.f, 0.f);
        for (int d = 0; d < 100; d += 2) {
            float2 v = *(const float2*)&s1R[tid * STR + d];
            a = ffma2(v, v, a);
        }
        sm[R1O + tid] = invs(a.x + a.y);
    } else if (tid < 150) {                  // 1/||s2_j||
        int j = tid - 50;
        float2 a = make_float2(0.f, 0.f);
        for (int d = 0; d < 100; d += 2) {
            float2 v = *(const float2*)&s2R[j * STR + d];
            a = ffma2(v, v, a);
        }
        sm[R2O + j] = invs(a.x + a.y);
    } else if (tid < 160) {                  // full's n2 on s2[99] per p
        int p = tid - 150;
        float acc = 0.f;
        for (int d = 0; d < 100; d++) {
            float v = s2R[99 * STR + d];
            float w = __ldg(&wf[p * 100 + d]);
            acc = fmaf(v * v, w * w, acc);
        }
        sm[R2FO + p] = invs(acc);
    } else if (tid < 220) {                  // weighted norms as 5x5 tiles
        int t = tid - 160;                   // 0..59 : 0..19 s1 (50 rows), 20..59 s2 (100 rows)
        int which = (t >= 20);
        int r = which ? (t - 20) : t;
        int i0 = (r / 2) * 5;
        int p0 = (r % 2) * 5;
        const float* base = which ? s2R : s1R;
        float2 acc[5][5];
        #pragma unroll
        for (int m = 0; m < 5; m++)
            #pragma unroll
            for (int q = 0; q < 5; q++) acc[m][q] = make_float2(0.f, 0.f);
        for (int d = 0; d < 100; d += 2) {
            float2 wv[5];
            #pragma unroll
            for (int q = 0; q < 5; q++)
                wv[q] = *(const float2*)&sm[WMO + (p0 + q) * 100 + d];
            #pragma unroll
            for (int m = 0; m < 5; m++) {
                float2 v = *(const float2*)&base[(i0 + m) * STR + d];
                float2 sq = fmul2(v, v);
                #pragma unroll
                for (int q = 0; q < 5; q++) acc[m][q] = ffma2(sq, wv[q], acc[m][q]);
            }
        }
        float* dst = sm + (which ? R2WO : R1WO);
        #pragma unroll
        for (int m = 0; m < 5; m++)
            #pragma unroll
            for (int q = 0; q < 5; q++)
                dst[(i0 + m) * 10 + p0 + q] = invs(acc[m][q].x + acc[m][q].y);
    }
    __syncthreads();

    // ====== phase 2: cosm GEMM (125 thr, 10x4 tile, float4 over d) ==========
    if (tid < 125) {
        const int ty = tid / 25;       // 0..4
        const int tx = tid - ty * 25;  // 0..24
        const int i0 = ty * 10;
        float2 acc[10][4];
        #pragma unroll
        for (int m = 0; m < 10; m++)
            #pragma unroll
            for (int n = 0; n < 4; n++) acc[m][n] = make_float2(0.f, 0.f);
        for (int d = 0; d < 100; d += 4) {
            float4 bv[4];
            #pragma unroll
            for (int n = 0; n < 4; n++)
                bv[n] = *(const float4*)&s2R[(tx + 25 * n) * STR + d];
            #pragma unroll
            for (int m = 0; m < 10; m++) {
                float4 a = *(const float4*)&s1R[(i0 + m) * STR + d];
                float2 alo = make_float2(a.x, a.y), ahi = make_float2(a.z, a.w);
                #pragma unroll
                for (int n = 0; n < 4; n++) {
                    acc[m][n] = ffma2(alo, make_float2(bv[n].x, bv[n].y), acc[m][n]);
                    acc[m][n] = ffma2(ahi, make_float2(bv[n].z, bv[n].w), acc[m][n]);
                }
            }
        }
        #pragma unroll
        for (int m = 0; m < 10; m++) {
            int ii = i0 + m;
            float r1 = sm[R1O + ii];
            #pragma unroll
            for (int n = 0; n < 4; n++) {
                int j = tx + 25 * n;
                cm[ii * STR + j] = (acc[m][n].x + acc[m][n].y) * r1 * sm[R2O + j];
            }
        }
    }
    __syncthreads();

    // ================= phase 3: rowsum + argmax (first-max) =================
    if (tid < 50) {
        float rs = 0.f, best = -1e30f; int bj = 0;
        for (int j = 0; j < 100; j++) {
            float v = cm[tid * STR + j];
            rs += v;
            if (v > best) { best = v; bj = j; }
        }
        sm[RSO + tid] = rs;
        reinterpret_cast<int*>(sm)[JMO + tid] = bj;
    }
    __syncthreads();

    // ====== phase 4: maxpool — 5 p-pairs, 250 thr, 5i x 4j x 2p tile ========
    // a-operand scaled by w (per p), raw s2 b-loads shared across both p.
    {
        const int ty = tid / 25;           // 0..9 (tid<250)
        const int tx = tid - ty * 25;      // 0..24
        const int i0 = ty * 5;
        for (int pi = 0; pi < 5; pi++) {
            if (tid < 250) {
                const int pA = pi * 2, pB = pA + 1;
                float2 accA[5][4], accB[5][4];
                #pragma unroll
                for (int m = 0; m < 5; m++)
                    #pragma unroll
                    for (int n = 0; n < 4; n++) {
                        accA[m][n] = make_float2(0.f, 0.f);
                        accB[m][n] = make_float2(0.f, 0.f);
                    }
                const float* wpA = sm + WMO + pA * 100;
                const float* wpB = sm + WMO + pB * 100;
                for (int d = 0; d < 100; d += 4) {
                    float4 wa4 = *(const float4*)&wpA[d];
                    float4 wb4 = *(const float4*)&wpB[d];
                    float2 wAlo = make_float2(wa4.x, wa4.y), wAhi = make_float2(wa4.z, wa4.w);
                    float2 wBlo = make_float2(wb4.x, wb4.y), wBhi = make_float2(wb4.z, wb4.w);
                    float2 blo[4], bhi[4];
                    #pragma unroll
                    for (int n = 0; n < 4; n++) {
                        float4 bv = *(const float4*)&s2R[(tx + 25 * n) * STR + d];
                        blo[n] = make_float2(bv.x, bv.y);
                        bhi[n] = make_float2(bv.z, bv.w);
                    }
                    #pragma unroll
                    for (int m = 0; m < 5; m++) {
                        float4 a = *(const float4*)&s1R[(i0 + m) * STR + d];
                        float2 alo = make_float2(a.x, a.y), ahi = make_float2(a.z, a.w);
                        float2 aAlo = fmul2(alo, wAlo), aAhi = fmul2(ahi, wAhi);
                        float2 aBlo = fmul2(alo, wBlo), aBhi = fmul2(ahi, wBhi);
                        #pragma unroll
                        for (int n = 0; n < 4; n++) {
                            accA[m][n] = ffma2(aAlo, blo[n], accA[m][n]);
                            accA[m][n] = ffma2(aAhi, bhi[n], accA[m][n]);
                            accB[m][n] = ffma2(aBlo, blo[n], accB[m][n]);
                            accB[m][n] = ffma2(aBhi, bhi[n], accB[m][n]);
                        }
                    }
                }
                #pragma unroll
                for (int m = 0; m < 5; m++) {
                    int ii = i0 + m;
                    float r1A = sm[R1WO + ii * 10 + pA];
                    float r1B = sm[R1WO + ii * 10 + pB];
                    float pmA = -1e30f, pmB = -1e30f;
                    #pragma unroll
                    for (int n = 0; n < 4; n++) {
                        int j = tx + 25 * n;
                        pmA = fmaxf(pmA, (accA[m][n].x + accA[m][n].y) * r1A * sm[R2WO + j * 10 + pA]);
                        pmB = fmaxf(pmB, (accB[m][n].x + accB[m][n].y) * r1B * sm[R2WO + j * 10 + pB]);
                    }
                    sm[MPO + ii * 25 + tx] = pmA;
                    sm[MPO + 1250 + ii * 25 + tx] = pmB;
                }
            }
            __syncthreads();
            if (tid < 100) {
                int g = tid / 50, ii = tid - g * 50;
                float mv = -1e30f;
                #pragma unroll 5
                for (int k = 0; k < 25; k++)
                    mv = fmaxf(mv, sm[MPO + g * 1250 + ii * 25 + k]);
                out[((size_t)(ib + ii) * 256 + b) * 80 + 20 + dir * 10 + (pi * 2 + g)] = mv;
            }
            __syncthreads();
        }
    }

    // ====== phase 5: mean attention GEMM (125 thr, 10x4, float4 over j) ====
    // att held in regs, then written over the cm buffer after a sync.
    float attv[10][4];
    const int ty5 = tid / 25, tx5 = tid - ty5 * 25, i05 = ty5 * 10;
    if (tid < 125) {
        float2 acc[10][4];
        #pragma unroll
        for (int m = 0; m < 10; m++)
            #pragma unroll
            for (int n = 0; n < 4; n++) acc[m][n] = make_float2(0.f, 0.f);
        for (int j = 0; j < 100; j += 4) {
            float2 blo[4], bhi[4];
            #pragma unroll
            for (int n = 0; n < 4; n++) {
                int dc = tx5 + 25 * n;
                blo[n] = make_float2(s2R[j * STR + dc],       s2R[(j + 1) * STR + dc]);
                bhi[n] = make_float2(s2R[(j + 2) * STR + dc], s2R[(j + 3) * STR + dc]);
            }
            #pragma unroll
            for (int m = 0; m < 10; m++) {
                float4 a = *(const float4*)&cm[(i05 + m) * STR + j];
                float2 alo = make_float2(a.x, a.y), ahi = make_float2(a.z, a.w);
                #pragma unroll
                for (int n = 0; n < 4; n++) {
                    acc[m][n] = ffma2(alo, blo[n], acc[m][n]);
                    acc[m][n] = ffma2(ahi, bhi[n], acc[m][n]);
                }
            }
        }
        #pragma unroll
        for (int m = 0; m < 10; m++) {
            float rd = 1.0f / (sm[RSO + i05 + m] + EPSf);
            #pragma unroll
            for (int n = 0; n < 4; n++)
                attv[m][n] = (acc[m][n].x + acc[m][n].y) * rd;
        }
    }
    __syncthreads();            // all cm reads done
    if (tid < 125) {
        #pragma unroll
        for (int m = 0; m < 10; m++)
            #pragma unroll
            for (int n = 0; n < 4; n++)
                cm[(i05 + m) * STR + tx5 + 25 * n] = attv[m][n];   // cm now holds att
    }
    __syncthreads();
    float* attS = cm;

    // ======== phase 6: features — full, mean-att, (dir==1) slot4 ===========
    for (int r = 0; r < 2; r++) {
        int task = tid + NT * r;
        if (task < 500) {
            int ii = task / 10, p = task - ii * 10;
            const float* wfp = wf + p * 100;
            const float* wep = we + p * 100;
            const float* wsp = ws + p * 100;
            float numF = 0.f, n1F = 0.f;
            float numE = 0.f, n1E = 0.f, n2E = 0.f;
            float numS = 0.f, n1S = 0.f, n2S = 0.f;
            for (int d = 0; d < 100; d++) {
                float v1 = s1R[ii * STR + d];
                float v2l = s2R[99 * STR + d];
                float av = attS[ii * STR + d];
                float wfv = __ldg(&wfp[d]); float wf2 = wfv * wfv;
                float wev = __ldg(&wep[d]); float we2 = wev * wev;
                numF = fmaf(v1 * v2l, wf2, numF);
                n1F  = fmaf(v1 * v1,  wf2, n1F);
                numE = fmaf(v1 * av,  we2, numE);
                n1E  = fmaf(v1 * v1,  we2, n1E);
                n2E  = fmaf(av * av,  we2, n2E);
                if (dir == 1) {
                    float wsv = __ldg(&wsp[d]); float ws2 = wsv * wsv;
                    numS = fmaf(v1 * av, ws2, numS);
                    n1S  = fmaf(v1 * v1, ws2, n1S);
                    n2S  = fmaf(av * av, ws2, n2S);
                }
            }
            size_t ob = ((size_t)(ib + ii) * 256 + b) * 80 + dir * 10 + p;
            out[ob +  0] = numF * invs(n1F) * sm[R2FO + p];
            out[ob + 40] = numE * invs(n1E) * invs(n2E);
            if (dir == 1)
                out[ob + 60] = numS * invs(n1S) * invs(n2S);
        }
    }

    // ======== phase 7 (dir==0 only): max-att features (ref bug kept) =======
    // att vector = s2[seq=0, batch=jmax, fwd slice] read straight from global
    if (dir == 0) {
        for (int r = 0; r < 2; r++) {
            int task = tid + NT * r;
            if (task < 500) {
                int ii = task / 10, p = task - ii * 10;
                int jm = reinterpret_cast<int*>(sm)[JMO + ii];
                const float* av_row = s2g + (size_t)jm * 200;
                const float* wsp = ws + p * 100;
                float num = 0.f, n1 = 0.f, n2 = 0.f;
                for (int d = 0; d < 100; d++) {
                    float v1 = s1R[ii * STR + d];
                    float av = __ldg(&av_row[d]);
                    float wsv = __ldg(&wsp[d]); float ws2 = wsv * wsv;
                    num = fmaf(v1 * av, ws2, num);
                    n1  = fmaf(v1 * v1, ws2, n1);
                    n2  = fmaf(av * av, ws2, n2);
                }
                out[((size_t)(ib + ii) * 256 + b) * 80 + 60 + p] = num * invs(n1) * invs(n2);
            }
        }
    }
}

extern "C" void kernel_launch(void* const* d_in, const int* in_sizes, int n_in,
                              void* d_out, int out_size) {
    const float* s1 = (const float*)d_in[0];
    const float* s2 = (const float*)d_in[1];
    const float* w1 = (const float*)d_in[2];
    const float* w2 = (const float*)d_in[3];
    const float* w3 = (const float*)d_in[4];
    const float* w4 = (const float*)d_in[5];
    const float* w5 = (const float*)d_in[6];
    const float* w6 = (const float*)d_in[7];
    const float* w7 = (const float*)d_in[8];
    const float* w8 = (const float*)d_in[9];
    float* out = (float*)d_out;

    static bool attr_set = false;
    if (!attr_set) {
        cudaFuncSetAttribute(matching_kernel,
                             cudaFuncAttributeMaxDynamicSharedMemorySize,
                             SMEM_FLOATS * (int)sizeof(float));
        attr_set = true;
    }
    dim3 grid(256, 2, 2);
    matching_kernel<<<grid, NT, SMEM_FLOATS * sizeof(float)>>>(
        s1, s2, w1, w2, w3, w4, w5, w6, w7, w8, out);
}

// round 13
// speedup vs baseline: 1.3329x; 1.3329x over previous
#include <cuda_runtime.h>
#include <math.h>
#include <stdint.h>

#define EPSf 1e-6f
#define NT 256
#define STR 108   // float4-aligned row stride; conflict-free for frag + float4 patterns

// ---- shared memory layout (float offsets) — 24,534 floats = 98 KB ----
#define S1O   0        // s1R[ii*108+d]  local 50 rows (5400)
#define S2O   5400     // s2R[j*108+d]   100 rows (10800)
#define CMO   16200    // cm[ii*108+j] (5400) — reused as att after phase 5
#define WMO   21600    // w_maxpool^2 [p*104+d] (1040), cols 100..103 zero
#define R1WO  22640    // 1/n1w [ii*10+p] (500)
#define R2WO  23140    // 1/n2w [j*10+p] (1000)
#define R1O   24140    // 1/||s1_ii|| (50)
#define R2O   24190    // 1/||s2_j|| (100)
#define RSO   24290    // rowsum per ii (50)
#define JMO   24340    // argmax j per ii (int) (50)
#define R2FO  24390    // full n2 per p (16)
#define MPO   24406    // maxpool scratch mp[64][2] (128)
#define SMEM_FLOATS 24534

__device__ __forceinline__ float invs(float x) { return 1.0f / sqrtf(fmaxf(x, EPSf)); }

__device__ __forceinline__ float2 ffma2(float2 a, float2 b, float2 c) {
    unsigned long long ua = *reinterpret_cast<unsigned long long*>(&a);
    unsigned long long ub = *reinterpret_cast<unsigned long long*>(&b);
    unsigned long long uc = *reinterpret_cast<unsigned long long*>(&c);
    unsigned long long ud;
    asm("fma.rn.f32x2 %0, %1, %2, %3;" : "=l"(ud) : "l"(ua), "l"(ub), "l"(uc));
    return *reinterpret_cast<float2*>(&ud);
}
__device__ __forceinline__ float2 fmul2(float2 a, float2 b) {
    unsigned long long ua = *reinterpret_cast<unsigned long long*>(&a);
    unsigned long long ub = *reinterpret_cast<unsigned long long*>(&b);
    unsigned long long ud;
    asm("mul.rn.f32x2 %0, %1, %2;" : "=l"(ud) : "l"(ua), "l"(ub));
    return *reinterpret_cast<float2*>(&ud);
}

// tf32 conversion (round-to-nearest — unbiased) and Ampere-style mma.sync
__device__ __forceinline__ uint32_t cvt_tf32(float x) {
    uint32_t u;
    asm("cvt.rna.tf32.f32 %0, %1;" : "=r"(u) : "f"(x));
    return u;
}
__device__ __forceinline__ void mma_tf32(float* c,
    uint32_t a0, uint32_t a1, uint32_t a2, uint32_t a3,
    uint32_t b0, uint32_t b1) {
    asm volatile(
        "mma.sync.aligned.m16n8k8.row.col.f32.tf32.tf32.f32 "
        "{%0,%1,%2,%3}, {%4,%5,%6,%7}, {%8,%9}, {%0,%1,%2,%3};"
        : "+f"(c[0]), "+f"(c[1]), "+f"(c[2]), "+f"(c[3])
        : "r"(a0), "r"(a1), "r"(a2), "r"(a3), "r"(b0), "r"(b1));
}

__global__ __launch_bounds__(NT, 2) void matching_kernel(
    const float* __restrict__ s1g, const float* __restrict__ s2g,
    const float* __restrict__ w1, const float* __restrict__ w2,
    const float* __restrict__ w3, const float* __restrict__ w4,
    const float* __restrict__ w5, const float* __restrict__ w6,
    const float* __restrict__ w7, const float* __restrict__ w8,
    float* __restrict__ out)
{
    extern __shared__ float sm[];
    const int b   = blockIdx.x;        // batch 0..255
    const int dir = blockIdx.y;        // 0=fwd, 1=bwd
    const int ib  = blockIdx.z * 50;   // i half: global rows [ib, ib+50)
    const int tid = threadIdx.x;
    const int dOff = dir * 100;

    float* s1R = sm + S1O;
    float* s2R = sm + S2O;
    float* cm  = sm + CMO;             // cm during phases 2-5, att afterwards

    const float* wf = dir ? w2 : w1;
    const float* wm = dir ? w4 : w3;
    const float* we = dir ? w6 : w5;
    const float* ws = dir ? w8 : w7;

    // ================= phase 0: wm^2 (stride 104, zero pad) + slices ========
    for (int e = tid; e < 1000; e += NT) {
        float a = wm[e];
        sm[WMO + (e / 100) * 104 + (e % 100)] = a * a;
    }
    if (tid < 40) sm[WMO + (tid >> 2) * 104 + 100 + (tid & 3)] = 0.f;
    for (int e = tid; e < 5000; e += NT) {
        int ii = e / 100, d = e - ii * 100;
        s1R[ii * STR + d] = s1g[((size_t)(ib + ii) * 256 + b) * 200 + dOff + d];
    }
    for (int e = tid; e < 10000; e += NT) {
        int j = e / 100, d = e - j * 100;
        s2R[j * STR + d] = s2g[((size_t)j * 256 + b) * 200 + dOff + d];
    }
    // zero d-pad cols 100..107 (K padding for mma)
    for (int e = tid; e < 400; e += NT) s1R[(e >> 3) * STR + 100 + (e & 7)] = 0.f;
    for (int e = tid; e < 800; e += NT) s2R[(e >> 3) * STR + 100 + (e & 7)] = 0.f;
    __syncthreads();

    // ================= phase 1: norms (parallel sub-jobs) ===================
    if (tid < 50) {                          // 1/||s1_ii||
        float2 a = make_float2(0.f, 0.f);
        for (int d = 0; d < 100; d += 2) {
            float2 v = *(const float2*)&s1R[tid * STR + d];
            a = ffma2(v, v, a);
        }
        sm[R1O + tid] = invs(a.x + a.y);
    } else if (tid < 150) {                  // 1/||s2_j||
        int j = tid - 50;
        float2 a = make_float2(0.f, 0.f);
        for (int d = 0; d < 100; d += 2) {
            float2 v = *(const float2*)&s2R[j * STR + d];
            a = ffma2(v, v, a);
        }
        sm[R2O + j] = invs(a.x + a.y);
    } else if (tid < 160) {                  // full's n2 on s2[99] per p
        int p = tid - 150;
        float acc = 0.f;
        for (int d = 0; d < 100; d++) {
            float v = s2R[99 * STR + d];
            float w = __ldg(&wf[p * 100 + d]);
            acc = fmaf(v * v, w * w, acc);
        }
        sm[R2FO + p] = invs(acc);
    } else if (tid < 220) {                  // weighted norms as 5x5 tiles
        int t = tid - 160;                   // 0..59 : 0..19 s1 (50 rows), 20..59 s2
        int which = (t >= 20);
        int r = which ? (t - 20) : t;
        int i0 = (r / 2) * 5;
        int p0 = (r % 2) * 5;
        const float* base = which ? s2R : s1R;
        float2 acc[5][5];
        #pragma unroll
        for (int m = 0; m < 5; m++)
            #pragma unroll
            for (int q = 0; q < 5; q++) acc[m][q] = make_float2(0.f, 0.f);
        for (int d = 0; d < 100; d += 2) {
            float2 wv[5];
            #pragma unroll
            for (int q = 0; q < 5; q++)
                wv[q] = *(const float2*)&sm[WMO + (p0 + q) * 104 + d];
            #pragma unroll
            for (int m = 0; m < 5; m++) {
                float2 v = *(const float2*)&base[(i0 + m) * STR + d];
                float2 sq = fmul2(v, v);
                #pragma unroll
                for (int q = 0; q < 5; q++) acc[m][q] = ffma2(sq, wv[q], acc[m][q]);
            }
        }
        float* dst = sm + (which ? R2WO : R1WO);
        #pragma unroll
        for (int m = 0; m < 5; m++)
            #pragma unroll
            for (int q = 0; q < 5; q++)
                dst[(i0 + m) * 10 + p0 + q] = invs(acc[m][q].x + acc[m][q].y);
    }
    __syncthreads();

    // ====== phase 2: cosm GEMM (125 thr, 10x4 tile, float4 over d) ==========
    if (tid < 125) {
        const int ty = tid / 25;       // 0..4
        const int tx = tid - ty * 25;  // 0..24
        const int i0 = ty * 10;
        float2 acc[10][4];
        #pragma unroll
        for (int m = 0; m < 10; m++)
            #pragma unroll
            for (int n = 0; n < 4; n++) acc[m][n] = make_float2(0.f, 0.f);
        for (int d = 0; d < 100; d += 4) {
            float4 bv[4];
            #pragma unroll
            for (int n = 0; n < 4; n++)
                bv[n] = *(const float4*)&s2R[(tx + 25 * n) * STR + d];
            #pragma unroll
            for (int m = 0; m < 10; m++) {
                float4 a = *(const float4*)&s1R[(i0 + m) * STR + d];
                float2 alo = make_float2(a.x, a.y), ahi = make_float2(a.z, a.w);
                #pragma unroll
                for (int n = 0; n < 4; n++) {
                    acc[m][n] = ffma2(alo, make_float2(bv[n].x, bv[n].y), acc[m][n]);
                    acc[m][n] = ffma2(ahi, make_float2(bv[n].z, bv[n].w), acc[m][n]);
                }
            }
        }
        #pragma unroll
        for (int m = 0; m < 10; m++) {
            int ii = i0 + m;
            float r1 = sm[R1O + ii];
            #pragma unroll
            for (int n = 0; n < 4; n++) {
                int j = tx + 25 * n;
                cm[ii * STR + j] = (acc[m][n].x + acc[m][n].y) * r1 * sm[R2O + j];
            }
        }
    }
    __syncthreads();

    // ================= phase 3: rowsum + argmax (first-max) =================
    if (tid < 50) {
        float rs = 0.f, best = -1e30f; int bj = 0;
        for (int j = 0; j < 100; j++) {
            float v = cm[tid * STR + j];
            rs += v;
            if (v > best) { best = v; bj = j; }
        }
        sm[RSO + tid] = rs;
        reinterpret_cast<int*>(sm)[JMO + tid] = bj;
    }
    __syncthreads();

    // ====== phase 4: maxpool via mma.sync tf32 HMMA =========================
    // C_p[i,j] = sum_d (s1[i,d]*w2[p,d]) * s2[j,d]; w2 folded into A frags.
    // 8 warps = (m-tile 0..3) x (n-half 0..1). M=64 (rows>=50 discarded),
    // N=104 (j>=100 masked), K=104 (d-pad zeroed).
    {
        const int lane = tid & 31;
        const int wid8 = tid >> 5;         // 0..7
        const int mt = wid8 & 3;
        const int nh = wid8 >> 2;
        const int ntiles = nh ? 6 : 7;
        const int j0w = nh * 56;           // nh0: j 0..55 (7 tiles), nh1: 56..103 (6)
        const int g = lane >> 2, tc = lane & 3;
        const int arow0 = (mt * 16 + g) * STR;
        const int arow1 = arow0 + 8 * STR;
        float* mp = sm + MPO;
        const int i0g = mt * 16 + g;
        const int i1g = i0g + 8;
        for (int p = 0; p < 10; p++) {
            float acc[7][4];
            #pragma unroll
            for (int n = 0; n < 7; n++) {
                acc[n][0] = 0.f; acc[n][1] = 0.f; acc[n][2] = 0.f; acc[n][3] = 0.f;
            }
            const float* wp = sm + WMO + p * 104;
            for (int k = 0; k < 13; k++) {
                int d0 = k * 8;
                float w0 = wp[d0 + tc], w1 = wp[d0 + tc + 4];
                uint32_t a0 = cvt_tf32(s1R[arow0 + d0 + tc] * w0);
                uint32_t a1 = cvt_tf32(s1R[arow1 + d0 + tc] * w0);
                uint32_t a2 = cvt_tf32(s1R[arow0 + d0 + tc + 4] * w1);
                uint32_t a3 = cvt_tf32(s1R[arow1 + d0 + tc + 4] * w1);
                #pragma unroll
                for (int n = 0; n < 7; n++) {
                    if (n < ntiles) {
                        int jrow = (j0w + n * 8 + g) * STR;
                        uint32_t b0 = cvt_tf32(s2R[jrow + d0 + tc]);
                        uint32_t b1 = cvt_tf32(s2R[jrow + d0 + tc + 4]);
                        mma_tf32(acc[n], a0, a1, a2, a3, b0, b1);
                    }
                }
            }
            // epilogue: scale by norms, mask pads, j-max in regs + shfl
            float pm0 = -1e30f, pm1 = -1e30f;
            float r1a = (i0g < 50) ? sm[R1WO + i0g * 10 + p] : 0.f;
            float r1b = (i1g < 50) ? sm[R1WO + i1g * 10 + p] : 0.f;
            #pragma unroll
            for (int n = 0; n < 7; n++) {
                if (n < ntiles) {
                    int j = j0w + n * 8 + 2 * tc;
                    if (j < 100) {
                        float r2 = sm[R2WO + j * 10 + p];
                        pm0 = fmaxf(pm0, acc[n][0] * r1a * r2);
                        pm1 = fmaxf(pm1, acc[n][2] * r1b * r2);
                    }
                    if (j + 1 < 100) {
                        float r2 = sm[R2WO + (j + 1) * 10 + p];
                        pm0 = fmaxf(pm0, acc[n][1] * r1a * r2);
                        pm1 = fmaxf(pm1, acc[n][3] * r1b * r2);
                    }
                }
            }
            pm0 = fmaxf(pm0, __shfl_xor_sync(0xffffffffu, pm0, 1));
            pm0 = fmaxf(pm0, __shfl_xor_sync(0xffffffffu, pm0, 2));
            pm1 = fmaxf(pm1, __shfl_xor_sync(0xffffffffu, pm1, 1));
            pm1 = fmaxf(pm1, __shfl_xor_sync(0xffffffffu, pm1, 2));
            if (tc == 0) {
                mp[i0g * 2 + nh] = pm0;
                mp[i1g * 2 + nh] = pm1;
            }
            __syncthreads();
            if (tid < 50) {
                float mv = fmaxf(mp[tid * 2 + 0], mp[tid * 2 + 1]);
                out[((size_t)(ib + tid) * 256 + b) * 80 + 20 + dir * 10 + p] = mv;
            }
            __syncthreads();
        }
    }

    // ====== phase 5: mean attention GEMM (125 thr, 10x4, float4 over j) ====
    float attv[10][4];
    const int ty5 = tid / 25, tx5 = tid - ty5 * 25, i05 = ty5 * 10;
    if (tid < 125) {
        float2 acc[10][4];
        #pragma unroll
        for (int m = 0; m < 10; m++)
            #pragma unroll
            for (int n = 0; n < 4; n++) acc[m][n] = make_float2(0.f, 0.f);
        for (int j = 0; j < 100; j += 4) {
            float2 blo[4], bhi[4];
            #pragma unroll
            for (int n = 0; n < 4; n++) {
                int dc = tx5 + 25 * n;
                blo[n] = make_float2(s2R[j * STR + dc],       s2R[(j + 1) * STR + dc]);
                bhi[n] = make_float2(s2R[(j + 2) * STR + dc], s2R[(j + 3) * STR + dc]);
            }
            #pragma unroll
            for (int m = 0; m < 10; m++) {
                float4 a = *(const float4*)&cm[(i05 + m) * STR + j];
                float2 alo = make_float2(a.x, a.y), ahi = make_float2(a.z, a.w);
                #pragma unroll
                for (int n = 0; n < 4; n++) {
                    acc[m][n] = ffma2(alo, blo[n], acc[m][n]);
                    acc[m][n] = ffma2(ahi, bhi[n], acc[m][n]);
                }
            }
        }
        #pragma unroll
        for (int m = 0; m < 10; m++) {
            float rd = 1.0f / (sm[RSO + i05 + m] + EPSf);
            #pragma unroll
            for (int n = 0; n < 4; n++)
                attv[m][n] = (acc[m][n].x + acc[m][n].y) * rd;
        }
    }
    __syncthreads();            // all cm reads done
    if (tid < 125) {
        #pragma unroll
        for (int m = 0; m < 10; m++)
            #pragma unroll
            for (int n = 0; n < 4; n++)
                cm[(i05 + m) * STR + tx5 + 25 * n] = attv[m][n];   // cm now holds att
    }
    __syncthreads();
    float* attS = cm;

    // ======== phase 6: features — full, mean-att, (dir==1) slot4 ===========
    for (int r = 0; r < 2; r++) {
        int task = tid + NT * r;
        if (task < 500) {
            int ii = task / 10, p = task - ii * 10;
            const float* wfp = wf + p * 100;
            const float* wep = we + p * 100;
            const float* wsp = ws + p * 100;
            float numF = 0.f, n1F = 0.f;
            float numE = 0.f, n1E = 0.f, n2E = 0.f;
            float numS = 0.f, n1S = 0.f, n2S = 0.f;
            for (int d = 0; d < 100; d++) {
                float v1 = s1R[ii * STR + d];
                float v2l = s2R[99 * STR + d];
                float av = attS[ii * STR + d];
                float wfv = __ldg(&wfp[d]); float wf2 = wfv * wfv;
                float wev = __ldg(&wep[d]); float we2 = wev * wev;
                numF = fmaf(v1 * v2l, wf2, numF);
                n1F  = fmaf(v1 * v1,  wf2, n1F);
                numE = fmaf(v1 * av,  we2, numE);
                n1E  = fmaf(v1 * v1,  we2, n1E);
                n2E  = fmaf(av * av,  we2, n2E);
                if (dir == 1) {
                    float wsv = __ldg(&wsp[d]); float ws2 = wsv * wsv;
                    numS = fmaf(v1 * av, ws2, numS);
                    n1S  = fmaf(v1 * v1, ws2, n1S);
                    n2S  = fmaf(av * av, ws2, n2S);
                }
            }
            size_t ob = ((size_t)(ib + ii) * 256 + b) * 80 + dir * 10 + p;
            out[ob +  0] = numF * invs(n1F) * sm[R2FO + p];
            out[ob + 40] = numE * invs(n1E) * invs(n2E);
            if (dir == 1)
                out[ob + 60] = numS * invs(n1S) * invs(n2S);
        }
    }

    // ======== phase 7 (dir==0 only): max-att features (ref bug kept) =======
    // att vector = s2[seq=0, batch=jmax, fwd slice] read straight from global
    if (dir == 0) {
        for (int r = 0; r < 2; r++) {
            int task = tid + NT * r;
            if (task < 500) {
                int ii = task / 10, p = task - ii * 10;
                int jm = reinterpret_cast<int*>(sm)[JMO + ii];
                const float* av_row = s2g + (size_t)jm * 200;
                const float* wsp = ws + p * 100;
                float num = 0.f, n1 = 0.f, n2 = 0.f;
                for (int d = 0; d < 100; d++) {
                    float v1 = s1R[ii * STR + d];
                    float av = __ldg(&av_row[d]);
                    float wsv = __ldg(&wsp[d]); float ws2 = wsv * wsv;
                    num = fmaf(v1 * av, ws2, num);
                    n1  = fmaf(v1 * v1, ws2, n1);
                    n2  = fmaf(av * av, ws2, n2);
                }
                out[((size_t)(ib + ii) * 256 + b) * 80 + 60 + p] = num * invs(n1) * invs(n2);
            }
        }
    }
}

extern "C" void kernel_launch(void* const* d_in, const int* in_sizes, int n_in,
                              void* d_out, int out_size) {
    const float* s1 = (const float*)d_in[0];
    const float* s2 = (const float*)d_in[1];
    const float* w1 = (const float*)d_in[2];
    const float* w2 = (const float*)d_in[3];
    const float* w3 = (const float*)d_in[4];
    const float* w4 = (const float*)d_in[5];
    const float* w5 = (const float*)d_in[6];
    const float* w6 = (const float*)d_in[7];
    const float* w7 = (const float*)d_in[8];
    const float* w8 = (const float*)d_in[9];
    float* out = (float*)d_out;

    static bool attr_set = false;
    if (!attr_set) {
        cudaFuncSetAttribute(matching_kernel,
                             cudaFuncAttributeMaxDynamicSharedMemorySize,
                             SMEM_FLOATS * (int)sizeof(float));
        attr_set = true;
    }
    dim3 grid(256, 2, 2);
    matching_kernel<<<grid, NT, SMEM_FLOATS * sizeof(float)>>>(
        s1, s2, w1, w2, w3, w4, w5, w6, w7, w8, out);
}

// round 14
// speedup vs baseline: 1.4905x; 1.1183x over previous
#include <cuda_runtime.h>
#include <math.h>
#include <stdint.h>

#define EPSf 1e-6f
#define NT 256
#define STR 108   // float4-aligned row stride; conflict-free for frag + float4 patterns

// ---- shared memory layout (float offsets) — 24,662 floats = 98.6 KB ----
#define S1O   0        // s1R[ii*108+d]  local 50 rows (5400)
#define S2O   5400     // s2R[j*108+d]   100 rows (10800)
#define CMO   16200    // cm[ii*108+j] (5400) — reused as att after phase 5
#define WMO   21600    // w_maxpool^2 [p*104+d] (1040), cols 100..103 zero
#define R1WO  22640    // 1/n1w [ii*10+p] (500)
#define R2WO  23140    // 1/n2w [j*10+p] (1000)
#define R1O   24140    // 1/||s1_ii|| (50)
#define R2O   24190    // 1/||s2_j|| (100)
#define RSO   24290    // rowsum per ii (50)
#define JMO   24340    // argmax j per ii (int) (50)
#define R2FO  24390    // full n2 per p (16)
#define MPO   24406    // maxpool scratch mp[64][2p][2nh] (256)
#define SMEM_FLOATS 24662

__device__ __forceinline__ float invs(float x) { return 1.0f / sqrtf(fmaxf(x, EPSf)); }

__device__ __forceinline__ float2 ffma2(float2 a, float2 b, float2 c) {
    unsigned long long ua = *reinterpret_cast<unsigned long long*>(&a);
    unsigned long long ub = *reinterpret_cast<unsigned long long*>(&b);
    unsigned long long uc = *reinterpret_cast<unsigned long long*>(&c);
    unsigned long long ud;
    asm("fma.rn.f32x2 %0, %1, %2, %3;" : "=l"(ud) : "l"(ua), "l"(ub), "l"(uc));
    return *reinterpret_cast<float2*>(&ud);
}
__device__ __forceinline__ float2 fmul2(float2 a, float2 b) {
    unsigned long long ua = *reinterpret_cast<unsigned long long*>(&a);
    unsigned long long ub = *reinterpret_cast<unsigned long long*>(&b);
    unsigned long long ud;
    asm("mul.rn.f32x2 %0, %1, %2;" : "=l"(ud) : "l"(ua), "l"(ub));
    return *reinterpret_cast<float2*>(&ud);
}

// tf32 conversion (round-to-nearest — unbiased) and Ampere-style mma.sync
__device__ __forceinline__ uint32_t cvt_tf32(float x) {
    uint32_t u;
    asm("cvt.rna.tf32.f32 %0, %1;" : "=r"(u) : "f"(x));
    return u;
}
__device__ __forceinline__ void mma_tf32(float* c,
    uint32_t a0, uint32_t a1, uint32_t a2, uint32_t a3,
    uint32_t b0, uint32_t b1) {
    asm volatile(
        "mma.sync.aligned.m16n8k8.row.col.f32.tf32.tf32.f32 "
        "{%0,%1,%2,%3}, {%4,%5,%6,%7}, {%8,%9}, {%0,%1,%2,%3};"
        : "+f"(c[0]), "+f"(c[1]), "+f"(c[2]), "+f"(c[3])
        : "r"(a0), "r"(a1), "r"(a2), "r"(a3), "r"(b0), "r"(b1));
}

__global__ __launch_bounds__(NT, 2) void matching_kernel(
    const float* __restrict__ s1g, const float* __restrict__ s2g,
    const float* __restrict__ w1, const float* __restrict__ w2,
    const float* __restrict__ w3, const float* __restrict__ w4,
    const float* __restrict__ w5, const float* __restrict__ w6,
    const float* __restrict__ w7, const float* __restrict__ w8,
    float* __restrict__ out)
{
    extern __shared__ float sm[];
    const int b   = blockIdx.x;        // batch 0..255
    const int dir = blockIdx.y;        // 0=fwd, 1=bwd
    const int ib  = blockIdx.z * 50;   // i half: global rows [ib, ib+50)
    const int tid = threadIdx.x;
    const int dOff = dir * 100;

    float* s1R = sm + S1O;
    float* s2R = sm + S2O;
    float* cm  = sm + CMO;             // cm during phases 2-5, att afterwards

    const float* wf = dir ? w2 : w1;
    const float* wm = dir ? w4 : w3;
    const float* we = dir ? w6 : w5;
    const float* ws = dir ? w8 : w7;

    // ================= phase 0: wm^2 (stride 104, zero pad) + slices ========
    for (int e = tid; e < 1000; e += NT) {
        float a = wm[e];
        sm[WMO + (e / 100) * 104 + (e % 100)] = a * a;
    }
    if (tid < 40) sm[WMO + (tid >> 2) * 104 + 100 + (tid & 3)] = 0.f;
    for (int e = tid; e < 5000; e += NT) {
        int ii = e / 100, d = e - ii * 100;
        s1R[ii * STR + d] = s1g[((size_t)(ib + ii) * 256 + b) * 200 + dOff + d];
    }
    for (int e = tid; e < 10000; e += NT) {
        int j = e / 100, d = e - j * 100;
        s2R[j * STR + d] = s2g[((size_t)j * 256 + b) * 200 + dOff + d];
    }
    // zero d-pad cols 100..107 (K padding for mma)
    for (int e = tid; e < 400; e += NT) s1R[(e >> 3) * STR + 100 + (e & 7)] = 0.f;
    for (int e = tid; e < 800; e += NT) s2R[(e >> 3) * STR + 100 + (e & 7)] = 0.f;
    __syncthreads();

    // ================= phase 1: norms (parallel sub-jobs) ===================
    if (tid < 50) {                          // 1/||s1_ii||
        float2 a = make_float2(0.f, 0.f);
        for (int d = 0; d < 100; d += 2) {
            float2 v = *(const float2*)&s1R[tid * STR + d];
            a = ffma2(v, v, a);
        }
        sm[R1O + tid] = invs(a.x + a.y);
    } else if (tid < 150) {                  // 1/||s2_j||
        int j = tid - 50;
        float2 a = make_float2(0.f, 0.f);
        for (int d = 0; d < 100; d += 2) {
            float2 v = *(const float2*)&s2R[j * STR + d];
            a = ffma2(v, v, a);
        }
        sm[R2O + j] = invs(a.x + a.y);
    } else if (tid < 160) {                  // full's n2 on s2[99] per p
        int p = tid - 150;
        float acc = 0.f;
        for (int d = 0; d < 100; d++) {
            float v = s2R[99 * STR + d];
            float w = __ldg(&wf[p * 100 + d]);
            acc = fmaf(v * v, w * w, acc);
        }
        sm[R2FO + p] = invs(acc);
    } else if (tid < 220) {                  // weighted norms as 5x5 tiles
        int t = tid - 160;                   // 0..59 : 0..19 s1 (50 rows), 20..59 s2
        int which = (t >= 20);
        int r = which ? (t - 20) : t;
        int i0 = (r / 2) * 5;
        int p0 = (r % 2) * 5;
        const float* base = which ? s2R : s1R;
        float2 acc[5][5];
        #pragma unroll
        for (int m = 0; m < 5; m++)
            #pragma unroll
            for (int q = 0; q < 5; q++) acc[m][q] = make_float2(0.f, 0.f);
        for (int d = 0; d < 100; d += 2) {
            float2 wv[5];
            #pragma unroll
            for (int q = 0; q < 5; q++)
                wv[q] = *(const float2*)&sm[WMO + (p0 + q) * 104 + d];
            #pragma unroll
            for (int m = 0; m < 5; m++) {
                float2 v = *(const float2*)&base[(i0 + m) * STR + d];
                float2 sq = fmul2(v, v);
                #pragma unroll
                for (int q = 0; q < 5; q++) acc[m][q] = ffma2(sq, wv[q], acc[m][q]);
            }
        }
        float* dst = sm + (which ? R2WO : R1WO);
        #pragma unroll
        for (int m = 0; m < 5; m++)
            #pragma unroll
            for (int q = 0; q < 5; q++)
                dst[(i0 + m) * 10 + p0 + q] = invs(acc[m][q].x + acc[m][q].y);
    }
    __syncthreads();

    // ====== phase 2: cosm GEMM (125 thr, 10x4 tile, float4 over d) ==========
    if (tid < 125) {
        const int ty = tid / 25;       // 0..4
        const int tx = tid - ty * 25;  // 0..24
        const int i0 = ty * 10;
        float2 acc[10][4];
        #pragma unroll
        for (int m = 0; m < 10; m++)
            #pragma unroll
            for (int n = 0; n < 4; n++) acc[m][n] = make_float2(0.f, 0.f);
        for (int d = 0; d < 100; d += 4) {
            float4 bv[4];
            #pragma unroll
            for (int n = 0; n < 4; n++)
                bv[n] = *(const float4*)&s2R[(tx + 25 * n) * STR + d];
            #pragma unroll
            for (int m = 0; m < 10; m++) {
                float4 a = *(const float4*)&s1R[(i0 + m) * STR + d];
                float2 alo = make_float2(a.x, a.y), ahi = make_float2(a.z, a.w);
                #pragma unroll
                for (int n = 0; n < 4; n++) {
                    acc[m][n] = ffma2(alo, make_float2(bv[n].x, bv[n].y), acc[m][n]);
                    acc[m][n] = ffma2(ahi, make_float2(bv[n].z, bv[n].w), acc[m][n]);
                }
            }
        }
        #pragma unroll
        for (int m = 0; m < 10; m++) {
            int ii = i0 + m;
            float r1 = sm[R1O + ii];
            #pragma unroll
            for (int n = 0; n < 4; n++) {
                int j = tx + 25 * n;
                cm[ii * STR + j] = (acc[m][n].x + acc[m][n].y) * r1 * sm[R2O + j];
            }
        }
    }
    __syncthreads();

    // ================= phase 3: rowsum + argmax (first-max) =================
    if (tid < 50) {
        float rs = 0.f, best = -1e30f; int bj = 0;
        for (int j = 0; j < 100; j++) {
            float v = cm[tid * STR + j];
            rs += v;
            if (v > best) { best = v; bj = j; }
        }
        sm[RSO + tid] = rs;
        reinterpret_cast<int*>(sm)[JMO + tid] = bj;
    }
    __syncthreads();

    // ====== phase 4: maxpool via mma.sync tf32, p-PAIRED (B shared) =========
    // C_p[i,j] = sum_d (s1[i,d]*w2[p,d]) * s2[j,d]; w2 folded into A frags.
    // 8 warps = (m-tile 0..3) x (n-half 0..1). Two p's per pass share all
    // B fragment loads + tf32 converts (they are p-independent).
    {
        const int lane = tid & 31;
        const int wid8 = tid >> 5;         // 0..7
        const int mt = wid8 & 3;
        const int nh = wid8 >> 2;
        const int ntiles = nh ? 6 : 7;
        const int j0w = nh * 56;           // nh0: j 0..55 (7 tiles), nh1: 56..103 (6)
        const int g = lane >> 2, tc = lane & 3;
        const int arow0 = (mt * 16 + g) * STR;
        const int arow1 = arow0 + 8 * STR;
        float* mp = sm + MPO;              // [i(64)][p-in-pair(2)][nh(2)]
        const int i0g = mt * 16 + g;
        const int i1g = i0g + 8;
        for (int pp = 0; pp < 5; pp++) {
            const int pA = pp * 2, pB = pA + 1;
            float accA[7][4], accB[7][4];
            #pragma unroll
            for (int n = 0; n < 7; n++)
                #pragma unroll
                for (int q = 0; q < 4; q++) { accA[n][q] = 0.f; accB[n][q] = 0.f; }
            const float* wpA = sm + WMO + pA * 104;
            const float* wpB = wpA + 104;
            for (int k = 0; k < 13; k++) {
                int d0 = k * 8;
                float s00 = s1R[arow0 + d0 + tc],     s10 = s1R[arow1 + d0 + tc];
                float s01 = s1R[arow0 + d0 + tc + 4], s11 = s1R[arow1 + d0 + tc + 4];
                float wA0 = wpA[d0 + tc], wA1 = wpA[d0 + tc + 4];
                float wB0 = wpB[d0 + tc], wB1 = wpB[d0 + tc + 4];
                uint32_t aA0 = cvt_tf32(s00 * wA0), aA1 = cvt_tf32(s10 * wA0);
                uint32_t aA2 = cvt_tf32(s01 * wA1), aA3 = cvt_tf32(s11 * wA1);
                uint32_t aB0 = cvt_tf32(s00 * wB0), aB1 = cvt_tf32(s10 * wB0);
                uint32_t aB2 = cvt_tf32(s01 * wB1), aB3 = cvt_tf32(s11 * wB1);
                #pragma unroll
                for (int n = 0; n < 7; n++) {
                    if (n < ntiles) {
                        int jrow = (j0w + n * 8 + g) * STR;
                        uint32_t b0 = cvt_tf32(s2R[jrow + d0 + tc]);
                        uint32_t b1 = cvt_tf32(s2R[jrow + d0 + tc + 4]);
                        mma_tf32(accA[n], aA0, aA1, aA2, aA3, b0, b1);
                        mma_tf32(accB[n], aB0, aB1, aB2, aB3, b0, b1);
                    }
                }
            }
            // epilogue: scale by norms, mask pads, j-max in regs + shfl, both p
            float pmA0 = -1e30f, pmA1 = -1e30f, pmB0 = -1e30f, pmB1 = -1e30f;
            float r1aA = (i0g < 50) ? sm[R1WO + i0g * 10 + pA] : 0.f;
            float r1bA = (i1g < 50) ? sm[R1WO + i1g * 10 + pA] : 0.f;
            float r1aB = (i0g < 50) ? sm[R1WO + i0g * 10 + pB] : 0.f;
            float r1bB = (i1g < 50) ? sm[R1WO + i1g * 10 + pB] : 0.f;
            #pragma unroll
            for (int n = 0; n < 7; n++) {
                if (n < ntiles) {
                    int j = j0w + n * 8 + 2 * tc;
                    if (j < 100) {
                        float r2A = sm[R2WO + j * 10 + pA];
                        float r2B = sm[R2WO + j * 10 + pB];
                        pmA0 = fmaxf(pmA0, accA[n][0] * r1aA * r2A);
                        pmA1 = fmaxf(pmA1, accA[n][2] * r1bA * r2A);
                        pmB0 = fmaxf(pmB0, accB[n][0] * r1aB * r2B);
                        pmB1 = fmaxf(pmB1, accB[n][2] * r1bB * r2B);
                    }
                    if (j + 1 < 100) {
                        float r2A = sm[R2WO + (j + 1) * 10 + pA];
                        float r2B = sm[R2WO + (j + 1) * 10 + pB];
                        pmA0 = fmaxf(pmA0, accA[n][1] * r1aA * r2A);
                        pmA1 = fmaxf(pmA1, accA[n][3] * r1bA * r2A);
                        pmB0 = fmaxf(pmB0, accB[n][1] * r1aB * r2B);
                        pmB1 = fmaxf(pmB1, accB[n][3] * r1bB * r2B);
                    }
                }
            }
            pmA0 = fmaxf(pmA0, __shfl_xor_sync(0xffffffffu, pmA0, 1));
            pmA0 = fmaxf(pmA0, __shfl_xor_sync(0xffffffffu, pmA0, 2));
            pmA1 = fmaxf(pmA1, __shfl_xor_sync(0xffffffffu, pmA1, 1));
            pmA1 = fmaxf(pmA1, __shfl_xor_sync(0xffffffffu, pmA1, 2));
            pmB0 = fmaxf(pmB0, __shfl_xor_sync(0xffffffffu, pmB0, 1));
            pmB0 = fmaxf(pmB0, __shfl_xor_sync(0xffffffffu, pmB0, 2));
            pmB1 = fmaxf(pmB1, __shfl_xor_sync(0xffffffffu, pmB1, 1));
            pmB1 = fmaxf(pmB1, __shfl_xor_sync(0xffffffffu, pmB1, 2));
            if (tc == 0) {
                mp[i0g * 4 + 0 + nh] = pmA0;
                mp[i1g * 4 + 0 + nh] = pmA1;
                mp[i0g * 4 + 2 + nh] = pmB0;
                mp[i1g * 4 + 2 + nh] = pmB1;
            }
            __syncthreads();
            if (tid < 100) {
                int q = tid / 50, ii = tid - q * 50;   // q: 0->pA, 1->pB
                float mv = fmaxf(mp[ii * 4 + q * 2], mp[ii * 4 + q * 2 + 1]);
                out[((size_t)(ib + ii) * 256 + b) * 80 + 20 + dir * 10 + pA + q] = mv;
            }
            __syncthreads();
        }
    }

    // ====== phase 5: mean attention GEMM (125 thr, 10x4, float4 over j) ====
    float attv[10][4];
    const int ty5 = tid / 25, tx5 = tid - ty5 * 25, i05 = ty5 * 10;
    if (tid < 125) {
        float2 acc[10][4];
        #pragma unroll
        for (int m = 0; m < 10; m++)
            #pragma unroll
            for (int n = 0; n < 4; n++) acc[m][n] = make_float2(0.f, 0.f);
        for (int j = 0; j < 100; j += 4) {
            float2 blo[4], bhi[4];
            #pragma unroll
            for (int n = 0; n < 4; n++) {
                int dc = tx5 + 25 * n;
                blo[n] = make_float2(s2R[j * STR + dc],       s2R[(j + 1) * STR + dc]);
                bhi[n] = make_float2(s2R[(j + 2) * STR + dc], s2R[(j + 3) * STR + dc]);
            }
            #pragma unroll
            for (int m = 0; m < 10; m++) {
                float4 a = *(const float4*)&cm[(i05 + m) * STR + j];
                float2 alo = make_float2(a.x, a.y), ahi = make_float2(a.z, a.w);
                #pragma unroll
                for (int n = 0; n < 4; n++) {
                    acc[m][n] = ffma2(alo, blo[n], acc[m][n]);
                    acc[m][n] = ffma2(ahi, bhi[n], acc[m][n]);
                }
            }
        }
        #pragma unroll
        for (int m = 0; m < 10; m++) {
            float rd = 1.0f / (sm[RSO + i05 + m] + EPSf);
            #pragma unroll
            for (int n = 0; n < 4; n++)
                attv[m][n] = (acc[m][n].x + acc[m][n].y) * rd;
        }
    }
    __syncthreads();            // all cm reads done
    if (tid < 125) {
        #pragma unroll
        for (int m = 0; m < 10; m++)
            #pragma unroll
            for (int n = 0; n < 4; n++)
                cm[(i05 + m) * STR + tx5 + 25 * n] = attv[m][n];   // cm now holds att
    }
    __syncthreads();
    float* attS = cm;

    // ======== phase 6: features — full, mean-att, (dir==1) slot4 ===========
    for (int r = 0; r < 2; r++) {
        int task = tid + NT * r;
        if (task < 500) {
            int ii = task / 10, p = task - ii * 10;
            const float* wfp = wf + p * 100;
            const float* wep = we + p * 100;
            const float* wsp = ws + p * 100;
            float numF = 0.f, n1F = 0.f;
            float numE = 0.f, n1E = 0.f, n2E = 0.f;
            float numS = 0.f, n1S = 0.f, n2S = 0.f;
            for (int d = 0; d < 100; d++) {
                float v1 = s1R[ii * STR + d];
                float v2l = s2R[99 * STR + d];
                float av = attS[ii * STR + d];
                float wfv = __ldg(&wfp[d]); float wf2 = wfv * wfv;
                float wev = __ldg(&wep[d]); float we2 = wev * wev;
                numF = fmaf(v1 * v2l, wf2, numF);
                n1F  = fmaf(v1 * v1,  wf2, n1F);
                numE = fmaf(v1 * av,  we2, numE);
                n1E  = fmaf(v1 * v1,  we2, n1E);
                n2E  = fmaf(av * av,  we2, n2E);
                if (dir == 1) {
                    float wsv = __ldg(&wsp[d]); float ws2 = wsv * wsv;
                    numS = fmaf(v1 * av, ws2, numS);
                    n1S  = fmaf(v1 * v1, ws2, n1S);
                    n2S  = fmaf(av * av, ws2, n2S);
                }
            }
            size_t ob = ((size_t)(ib + ii) * 256 + b) * 80 + dir * 10 + p;
            out[ob +  0] = numF * invs(n1F) * sm[R2FO + p];
            out[ob + 40] = numE * invs(n1E) * invs(n2E);
            if (dir == 1)
                out[ob + 60] = numS * invs(n1S) * invs(n2S);
        }
    }

    // ======== phase 7 (dir==0 only): max-att features (ref bug kept) =======
    // att vector = s2[seq=0, batch=jmax, fwd slice] read straight from global
    if (dir == 0) {
        for (int r = 0; r < 2; r++) {
            int task = tid + NT * r;
            if (task < 500) {
                int ii = task / 10, p = task - ii * 10;
                int jm = reinterpret_cast<int*>(sm)[JMO + ii];
                const float* av_row = s2g + (size_t)jm * 200;
                const float* wsp = ws + p * 100;
                float num = 0.f, n1 = 0.f, n2 = 0.f;
                for (int d = 0; d < 100; d++) {
                    float v1 = s1R[ii * STR + d];
                    float av = __ldg(&av_row[d]);
                    float wsv = __ldg(&wsp[d]); float ws2 = wsv * wsv;
                    num = fmaf(v1 * av, ws2, num);
                    n1  = fmaf(v1 * v1, ws2, n1);
                    n2  = fmaf(av * av, ws2, n2);
                }
                out[((size_t)(ib + ii) * 256 + b) * 80 + 60 + p] = num * invs(n1) * invs(n2);
            }
        }
    }
}

extern "C" void kernel_launch(void* const* d_in, const int* in_sizes, int n_in,
                              void* d_out, int out_size) {
    const float* s1 = (const float*)d_in[0];
    const float* s2 = (const float*)d_in[1];
    const float* w1 = (const float*)d_in[2];
    const float* w2 = (const float*)d_in[3];
    const float* w3 = (const float*)d_in[4];
    const float* w4 = (const float*)d_in[5];
    const float* w5 = (const float*)d_in[6];
    const float* w6 = (const float*)d_in[7];
    const float* w7 = (const float*)d_in[8];
    const float* w8 = (const float*)d_in[9];
    float* out = (float*)d_out;

    static bool attr_set = false;
    if (!attr_set) {
        cudaFuncSetAttribute(matching_kernel,
                             cudaFuncAttributeMaxDynamicSharedMemorySize,
                             SMEM_FLOATS * (int)sizeof(float));
        attr_set = true;
    }
    dim3 grid(256, 2, 2);
    matching_kernel<<<grid, NT, SMEM_FLOATS * sizeof(float)>>>(
        s1, s2, w1, w2, w3, w4, w5, w6, w7, w8, out);
}

// round 15
// speedup vs baseline: 1.5894x; 1.0664x over previous
#include <cuda_runtime.h>
#include <math.h>
#include <stdint.h>

#define EPSf 1e-6f
#define NT 256
#define STR 108   // float4-aligned row stride; conflict-free for frag + float4 patterns

// ---- shared memory layout (float offsets) — 25,094 floats = 100.4 KB ----
#define S1O   0        // s1R[ii*108+d]  local 50 rows (5400)
#define S2O   5400     // s2R[j*108+d]   104 rows (11232), rows 100..103 zero
#define CMO   16632    // cm[ii*108+j] (5400) — reused as att after phase 5
#define WMO   22032    // w_maxpool^2 [p*104+d] (1040), cols 100..103 zero
#define R1WO  23072    // 1/n1w [ii*10+p] (500)
#define R2WO  23572    // 1/n2w [j*10+p] (1000)
#define R1O   24572    // 1/||s1_ii|| (50)
#define R2O   24622    // 1/||s2_j|| (100)
#define RSO   24722    // rowsum per ii (50)
#define JMO   24772    // argmax j per ii (int) (50)
#define R2FO  24822    // full n2 per p (16)
#define MPO   24838    // maxpool scratch mp[64][2p][2nh] (256)
#define SMEM_FLOATS 25094

__device__ __forceinline__ float invs(float x) { return 1.0f / sqrtf(fmaxf(x, EPSf)); }

__device__ __forceinline__ float2 ffma2(float2 a, float2 b, float2 c) {
    unsigned long long ua = *reinterpret_cast<unsigned long long*>(&a);
    unsigned long long ub = *reinterpret_cast<unsigned long long*>(&b);
    unsigned long long uc = *reinterpret_cast<unsigned long long*>(&c);
    unsigned long long ud;
    asm("fma.rn.f32x2 %0, %1, %2, %3;" : "=l"(ud) : "l"(ua), "l"(ub), "l"(uc));
    return *reinterpret_cast<float2*>(&ud);
}
__device__ __forceinline__ float2 fmul2(float2 a, float2 b) {
    unsigned long long ua = *reinterpret_cast<unsigned long long*>(&a);
    unsigned long long ub = *reinterpret_cast<unsigned long long*>(&b);
    unsigned long long ud;
    asm("mul.rn.f32x2 %0, %1, %2;" : "=l"(ud) : "l"(ua), "l"(ub));
    return *reinterpret_cast<float2*>(&ud);
}

// tf32 conversion (round-to-nearest — unbiased) and Ampere-style mma.sync
__device__ __forceinline__ uint32_t cvt_tf32(float x) {
    uint32_t u;
    asm("cvt.rna.tf32.f32 %0, %1;" : "=r"(u) : "f"(x));
    return u;
}
__device__ __forceinline__ void mma_tf32(float* c,
    uint32_t a0, uint32_t a1, uint32_t a2, uint32_t a3,
    uint32_t b0, uint32_t b1) {
    asm volatile(
        "mma.sync.aligned.m16n8k8.row.col.f32.tf32.tf32.f32 "
        "{%0,%1,%2,%3}, {%4,%5,%6,%7}, {%8,%9}, {%0,%1,%2,%3};"
        : "+f"(c[0]), "+f"(c[1]), "+f"(c[2]), "+f"(c[3])
        : "r"(a0), "r"(a1), "r"(a2), "r"(a3), "r"(b0), "r"(b1));
}

__global__ __launch_bounds__(NT, 2) void matching_kernel(
    const float* __restrict__ s1g, const float* __restrict__ s2g,
    const float* __restrict__ w1, const float* __restrict__ w2,
    const float* __restrict__ w3, const float* __restrict__ w4,
    const float* __restrict__ w5, const float* __restrict__ w6,
    const float* __restrict__ w7, const float* __restrict__ w8,
    float* __restrict__ out)
{
    extern __shared__ float sm[];
    const int b   = blockIdx.x;        // batch 0..255
    const int dir = blockIdx.y;        // 0=fwd, 1=bwd
    const int ib  = blockIdx.z * 50;   // i half: global rows [ib, ib+50)
    const int tid = threadIdx.x;
    const int dOff = dir * 100;

    float* s1R = sm + S1O;
    float* s2R = sm + S2O;
    float* cm  = sm + CMO;             // cm during phases 2-5, att afterwards

    const float* wf = dir ? w2 : w1;
    const float* wm = dir ? w4 : w3;
    const float* we = dir ? w6 : w5;
    const float* ws = dir ? w8 : w7;

    // ================= phase 0: wm^2 (stride 104, zero pad) + slices ========
    for (int e = tid; e < 1000; e += NT) {
        float a = wm[e];
        sm[WMO + (e / 100) * 104 + (e % 100)] = a * a;
    }
    if (tid < 40) sm[WMO + (tid >> 2) * 104 + 100 + (tid & 3)] = 0.f;
    for (int e = tid; e < 5000; e += NT) {
        int ii = e / 100, d = e - ii * 100;
        s1R[ii * STR + d] = s1g[((size_t)(ib + ii) * 256 + b) * 200 + dOff + d];
    }
    for (int e = tid; e < 10000; e += NT) {
        int j = e / 100, d = e - j * 100;
        s2R[j * STR + d] = s2g[((size_t)j * 256 + b) * 200 + dOff + d];
    }
    // zero d-pad cols 100..107 (K padding for mma)
    for (int e = tid; e < 400; e += NT) s1R[(e >> 3) * STR + 100 + (e & 7)] = 0.f;
    for (int e = tid; e < 800; e += NT) s2R[(e >> 3) * STR + 100 + (e & 7)] = 0.f;
    // zero s2 pad rows 100..103 (K padding for phase-5 mma)
    for (int e = tid; e < 432; e += NT) s2R[100 * STR + e] = 0.f;
    __syncthreads();

    // ================= phase 1: norms (parallel sub-jobs) ===================
    if (tid < 50) {                          // 1/||s1_ii||
        float2 a = make_float2(0.f, 0.f);
        for (int d = 0; d < 100; d += 2) {
            float2 v = *(const float2*)&s1R[tid * STR + d];
            a = ffma2(v, v, a);
        }
        sm[R1O + tid] = invs(a.x + a.y);
    } else if (tid < 150) {                  // 1/||s2_j||
        int j = tid - 50;
        float2 a = make_float2(0.f, 0.f);
        for (int d = 0; d < 100; d += 2) {
            float2 v = *(const float2*)&s2R[j * STR + d];
            a = ffma2(v, v, a);
        }
        sm[R2O + j] = invs(a.x + a.y);
    } else if (tid < 160) {                  // full's n2 on s2[99] per p
        int p = tid - 150;
        float acc = 0.f;
        for (int d = 0; d < 100; d++) {
            float v = s2R[99 * STR + d];
            float w = __ldg(&wf[p * 100 + d]);
            acc = fmaf(v * v, w * w, acc);
        }
        sm[R2FO + p] = invs(acc);
    } else if (tid < 220) {                  // weighted norms as 5x5 tiles
        int t = tid - 160;                   // 0..59 : 0..19 s1 (50 rows), 20..59 s2
        int which = (t >= 20);
        int r = which ? (t - 20) : t;
        int i0 = (r / 2) * 5;
        int p0 = (r % 2) * 5;
        const float* base = which ? s2R : s1R;
        float2 acc[5][5];
        #pragma unroll
        for (int m = 0; m < 5; m++)
            #pragma unroll
            for (int q = 0; q < 5; q++) acc[m][q] = make_float2(0.f, 0.f);
        for (int d = 0; d < 100; d += 2) {
            float2 wv[5];
            #pragma unroll
            for (int q = 0; q < 5; q++)
                wv[q] = *(const float2*)&sm[WMO + (p0 + q) * 104 + d];
            #pragma unroll
            for (int m = 0; m < 5; m++) {
                float2 v = *(const float2*)&base[(i0 + m) * STR + d];
                float2 sq = fmul2(v, v);
                #pragma unroll
                for (int q = 0; q < 5; q++) acc[m][q] = ffma2(sq, wv[q], acc[m][q]);
            }
        }
        float* dst = sm + (which ? R2WO : R1WO);
        #pragma unroll
        for (int m = 0; m < 5; m++)
            #pragma unroll
            for (int q = 0; q < 5; q++)
                dst[(i0 + m) * 10 + p0 + q] = invs(acc[m][q].x + acc[m][q].y);
    }
    __syncthreads();

    // ====== phase 2: cosm GEMM (125 thr, 10x4 tile, float4 over d) ==========
    if (tid < 125) {
        const int ty = tid / 25;       // 0..4
        const int tx = tid - ty * 25;  // 0..24
        const int i0 = ty * 10;
        float2 acc[10][4];
        #pragma unroll
        for (int m = 0; m < 10; m++)
            #pragma unroll
            for (int n = 0; n < 4; n++) acc[m][n] = make_float2(0.f, 0.f);
        for (int d = 0; d < 100; d += 4) {
            float4 bv[4];
            #pragma unroll
            for (int n = 0; n < 4; n++)
                bv[n] = *(const float4*)&s2R[(tx + 25 * n) * STR + d];
            #pragma unroll
            for (int m = 0; m < 10; m++) {
                float4 a = *(const float4*)&s1R[(i0 + m) * STR + d];
                float2 alo = make_float2(a.x, a.y), ahi = make_float2(a.z, a.w);
                #pragma unroll
                for (int n = 0; n < 4; n++) {
                    acc[m][n] = ffma2(alo, make_float2(bv[n].x, bv[n].y), acc[m][n]);
                    acc[m][n] = ffma2(ahi, make_float2(bv[n].z, bv[n].w), acc[m][n]);
                }
            }
        }
        #pragma unroll
        for (int m = 0; m < 10; m++) {
            int ii = i0 + m;
            float r1 = sm[R1O + ii];
            #pragma unroll
            for (int n = 0; n < 4; n++) {
                int j = tx + 25 * n;
                cm[ii * STR + j] = (acc[m][n].x + acc[m][n].y) * r1 * sm[R2O + j];
            }
        }
    }
    // zero cm K-pad cols 100..103 (phase-5 mma)
    if (tid < 200) cm[(tid >> 2) * STR + 100 + (tid & 3)] = 0.f;
    __syncthreads();

    // ================= phase 3: rowsum + argmax (first-max, exact) ==========
    if (tid < 50) {
        float rs = 0.f, best = -1e30f; int bj = 0;
        for (int j = 0; j < 100; j++) {
            float v = cm[tid * STR + j];
            rs += v;
            if (v > best) { best = v; bj = j; }
        }
        sm[RSO + tid] = rs;
        reinterpret_cast<int*>(sm)[JMO + tid] = bj;
    }
    __syncthreads();

    // ====== phase 3.5: pre-round s2R and cm to tf32 in place ================
    // (argmax/rowsum already taken from exact values; all remaining consumers
    //  are ratio-normalized cosines — ~1e-4 relative effect.)
    for (int e = tid; e < 10800; e += NT)
        s2R[e] = __uint_as_float(cvt_tf32(s2R[e]));
    for (int e = tid; e < 5400; e += NT)
        cm[e] = __uint_as_float(cvt_tf32(cm[e]));
    __syncthreads();

    // ====== phase 4: maxpool via mma.sync tf32, p-PAIRED (B shared, no cvt) =
    {
        const int lane = tid & 31;
        const int wid8 = tid >> 5;         // 0..7
        const int mt = wid8 & 3;
        const int nh = wid8 >> 2;
        const int ntiles = nh ? 6 : 7;
        const int j0w = nh * 56;           // nh0: j 0..55 (7 tiles), nh1: 56..103 (6)
        const int g = lane >> 2, tc = lane & 3;
        const int arow0 = (mt * 16 + g) * STR;
        const int arow1 = arow0 + 8 * STR;
        float* mp = sm + MPO;              // [i(64)][p-in-pair(2)][nh(2)]
        const int i0g = mt * 16 + g;
        const int i1g = i0g + 8;
        for (int pp = 0; pp < 5; pp++) {
            const int pA = pp * 2, pB = pA + 1;
            float accA[7][4], accB[7][4];
            #pragma unroll
            for (int n = 0; n < 7; n++)
                #pragma unroll
                for (int q = 0; q < 4; q++) { accA[n][q] = 0.f; accB[n][q] = 0.f; }
            const float* wpA = sm + WMO + pA * 104;
            const float* wpB = wpA + 104;
            for (int k = 0; k < 13; k++) {
                int d0 = k * 8;
                float s00 = s1R[arow0 + d0 + tc],     s10 = s1R[arow1 + d0 + tc];
                float s01 = s1R[arow0 + d0 + tc + 4], s11 = s1R[arow1 + d0 + tc + 4];
                float wA0 = wpA[d0 + tc], wA1 = wpA[d0 + tc + 4];
                float wB0 = wpB[d0 + tc], wB1 = wpB[d0 + tc + 4];
                uint32_t aA0 = cvt_tf32(s00 * wA0), aA1 = cvt_tf32(s10 * wA0);
                uint32_t aA2 = cvt_tf32(s01 * wA1), aA3 = cvt_tf32(s11 * wA1);
                uint32_t aB0 = cvt_tf32(s00 * wB0), aB1 = cvt_tf32(s10 * wB0);
                uint32_t aB2 = cvt_tf32(s01 * wB1), aB3 = cvt_tf32(s11 * wB1);
                #pragma unroll
                for (int n = 0; n < 7; n++) {
                    if (n < ntiles) {
                        int jrow = (j0w + n * 8 + g) * STR;
                        uint32_t b0 = __float_as_uint(s2R[jrow + d0 + tc]);
                        uint32_t b1 = __float_as_uint(s2R[jrow + d0 + tc + 4]);
                        mma_tf32(accA[n], aA0, aA1, aA2, aA3, b0, b1);
                        mma_tf32(accB[n], aB0, aB1, aB2, aB3, b0, b1);
                    }
                }
            }
            // epilogue: scale by norms, mask pads, j-max in regs + shfl, both p
            float pmA0 = -1e30f, pmA1 = -1e30f, pmB0 = -1e30f, pmB1 = -1e30f;
            float r1aA = (i0g < 50) ? sm[R1WO + i0g * 10 + pA] : 0.f;
            float r1bA = (i1g < 50) ? sm[R1WO + i1g * 10 + pA] : 0.f;
            float r1aB = (i0g < 50) ? sm[R1WO + i0g * 10 + pB] : 0.f;
            float r1bB = (i1g < 50) ? sm[R1WO + i1g * 10 + pB] : 0.f;
            #pragma unroll
            for (int n = 0; n < 7; n++) {
                if (n < ntiles) {
                    int j = j0w + n * 8 + 2 * tc;
                    if (j < 100) {
                        float r2A = sm[R2WO + j * 10 + pA];
                        float r2B = sm[R2WO + j * 10 + pB];
                        pmA0 = fmaxf(pmA0, accA[n][0] * r1aA * r2A);
                        pmA1 = fmaxf(pmA1, accA[n][2] * r1bA * r2A);
                        pmB0 = fmaxf(pmB0, accB[n][0] * r1aB * r2B);
                        pmB1 = fmaxf(pmB1, accB[n][2] * r1bB * r2B);
                    }
                    if (j + 1 < 100) {
                        float r2A = sm[R2WO + (j + 1) * 10 + pA];
                        float r2B = sm[R2WO + (j + 1) * 10 + pB];
                        pmA0 = fmaxf(pmA0, accA[n][1] * r1aA * r2A);
                        pmA1 = fmaxf(pmA1, accA[n][3] * r1bA * r2A);
                        pmB0 = fmaxf(pmB0, accB[n][1] * r1aB * r2B);
                        pmB1 = fmaxf(pmB1, accB[n][3] * r1bB * r2B);
                    }
                }
            }
            pmA0 = fmaxf(pmA0, __shfl_xor_sync(0xffffffffu, pmA0, 1));
            pmA0 = fmaxf(pmA0, __shfl_xor_sync(0xffffffffu, pmA0, 2));
            pmA1 = fmaxf(pmA1, __shfl_xor_sync(0xffffffffu, pmA1, 1));
            pmA1 = fmaxf(pmA1, __shfl_xor_sync(0xffffffffu, pmA1, 2));
            pmB0 = fmaxf(pmB0, __shfl_xor_sync(0xffffffffu, pmB0, 1));
            pmB0 = fmaxf(pmB0, __shfl_xor_sync(0xffffffffu, pmB0, 2));
            pmB1 = fmaxf(pmB1, __shfl_xor_sync(0xffffffffu, pmB1, 1));
            pmB1 = fmaxf(pmB1, __shfl_xor_sync(0xffffffffu, pmB1, 2));
            if (tc == 0) {
                mp[i0g * 4 + 0 + nh] = pmA0;
                mp[i1g * 4 + 0 + nh] = pmA1;
                mp[i0g * 4 + 2 + nh] = pmB0;
                mp[i1g * 4 + 2 + nh] = pmB1;
            }
            __syncthreads();
            if (tid < 100) {
                int q = tid / 50, ii = tid - q * 50;   // q: 0->pA, 1->pB
                float mv = fmaxf(mp[ii * 4 + q * 2], mp[ii * 4 + q * 2 + 1]);
                out[((size_t)(ib + ii) * 256 + b) * 80 + 20 + dir * 10 + pA + q] = mv;
            }
            __syncthreads();
        }
    }

    // ====== phase 5: mean attention via mma.sync tf32 (no cvt at all) ======
    // att[i][d] = (sum_j cm[i][j] * s2[j][d]) / (rowsum[i]+EPS)
    // A = cm (row-major, K=j, pre-rounded), B = s2 (col-major over K=j).
    {
        const int lane = tid & 31;
        const int wid8 = tid >> 5;
        const int mt = wid8 & 3;
        const int nh = wid8 >> 2;
        const int ntiles = nh ? 6 : 7;
        const int dbase0 = nh * 56;
        const int g = lane >> 2, tc = lane & 3;
        const int arow0 = (mt * 16 + g) * STR;
        const int arow1 = arow0 + 8 * STR;
        const int i0g = mt * 16 + g;
        const int i1g = i0g + 8;
        float acc[7][4];
        #pragma unroll
        for (int n = 0; n < 7; n++)
            #pragma unroll
            for (int q = 0; q < 4; q++) acc[n][q] = 0.f;
        for (int k = 0; k < 13; k++) {
            int k0 = k * 8;
            uint32_t a0 = __float_as_uint(cm[arow0 + k0 + tc]);
            uint32_t a1 = __float_as_uint(cm[arow1 + k0 + tc]);
            uint32_t a2 = __float_as_uint(cm[arow0 + k0 + tc + 4]);
            uint32_t a3 = __float_as_uint(cm[arow1 + k0 + tc + 4]);
            #pragma unroll
            for (int n = 0; n < 7; n++) {
                if (n < ntiles) {
                    int dc = dbase0 + n * 8 + g;
                    uint32_t b0 = __float_as_uint(s2R[(k0 + tc) * STR + dc]);
                    uint32_t b1 = __float_as_uint(s2R[(k0 + tc + 4) * STR + dc]);
                    mma_tf32(acc[n], a0, a1, a2, a3, b0, b1);
                }
            }
        }
        __syncthreads();        // all cm reads complete before att overwrites it
        float rd0 = (i0g < 50) ? 1.0f / (sm[RSO + i0g] + EPSf) : 0.f;
        float rd1 = (i1g < 50) ? 1.0f / (sm[RSO + i1g] + EPSf) : 0.f;
        #pragma unroll
        for (int n = 0; n < 7; n++) {
            if (n < ntiles) {
                int d1 = dbase0 + n * 8 + 2 * tc;
                if (i0g < 50) {
                    if (d1 < 100)     cm[i0g * STR + d1]     = acc[n][0] * rd0;
                    if (d1 + 1 < 100) cm[i0g * STR + d1 + 1] = acc[n][1] * rd0;
                }
                if (i1g < 50) {
                    if (d1 < 100)     cm[i1g * STR + d1]     = acc[n][2] * rd1;
                    if (d1 + 1 < 100) cm[i1g * STR + d1 + 1] = acc[n][3] * rd1;
                }
            }
        }
    }
    __syncthreads();
    float* attS = cm;

    // ======== phase 6: features — full, mean-att, (dir==1) slot4 ===========
    for (int r = 0; r < 2; r++) {
        int task = tid + NT * r;
        if (task < 500) {
            int ii = task / 10, p = task - ii * 10;
            const float* wfp = wf + p * 100;
            const float* wep = we + p * 100;
            const float* wsp = ws + p * 100;
            float numF = 0.f, n1F = 0.f;
            float numE = 0.f, n1E = 0.f, n2E = 0.f;
            float numS = 0.f, n1S = 0.f, n2S = 0.f;
            for (int d = 0; d < 100; d++) {
                float v1 = s1R[ii * STR + d];
                float v2l = s2R[99 * STR + d];
                float av = attS[ii * STR + d];
                float wfv = __ldg(&wfp[d]); float wf2 = wfv * wfv;
                float wev = __ldg(&wep[d]); float we2 = wev * wev;
                numF = fmaf(v1 * v2l, wf2, numF);
                n1F  = fmaf(v1 * v1,  wf2, n1F);
                numE = fmaf(v1 * av,  we2, numE);
                n1E  = fmaf(v1 * v1,  we2, n1E);
                n2E  = fmaf(av * av,  we2, n2E);
                if (dir == 1) {
                    float wsv = __ldg(&wsp[d]); float ws2 = wsv * wsv;
                    numS = fmaf(v1 * av, ws2, numS);
                    n1S  = fmaf(v1 * v1, ws2, n1S);
                    n2S  = fmaf(av * av, ws2, n2S);
                }
            }
            size_t ob = ((size_t)(ib + ii) * 256 + b) * 80 + dir * 10 + p;
            out[ob +  0] = numF * invs(n1F) * sm[R2FO + p];
            out[ob + 40] = numE * invs(n1E) * invs(n2E);
            if (dir == 1)
                out[ob + 60] = numS * invs(n1S) * invs(n2S);
        }
    }

    // ======== phase 7 (dir==0 only): max-att features (ref bug kept) =======
    // att vector = s2[seq=0, batch=jmax, fwd slice] read straight from global
    if (dir == 0) {
        for (int r = 0; r < 2; r++) {
            int task = tid + NT * r;
            if (task < 500) {
                int ii = task / 10, p = task - ii * 10;
                int jm = reinterpret_cast<int*>(sm)[JMO + ii];
                const float* av_row = s2g + (size_t)jm * 200;
                const float* wsp = ws + p * 100;
                float num = 0.f, n1 = 0.f, n2 = 0.f;
                for (int d = 0; d < 100; d++) {
                    float v1 = s1R[ii * STR + d];
                    float av = __ldg(&av_row[d]);
                    float wsv = __ldg(&wsp[d]); float ws2 = wsv * wsv;
                    num = fmaf(v1 * av, ws2, num);
                    n1  = fmaf(v1 * v1, ws2, n1);
                    n2  = fmaf(av * av, ws2, n2);
                }
                out[((size_t)(ib + ii) * 256 + b) * 80 + 60 + p] = num * invs(n1) * invs(n2);
            }
        }
    }
}

extern "C" void kernel_launch(void* const* d_in, const int* in_sizes, int n_in,
                              void* d_out, int out_size) {
    const float* s1 = (const float*)d_in[0];
    const float* s2 = (const float*)d_in[1];
    const float* w1 = (const float*)d_in[2];
    const float* w2 = (const float*)d_in[3];
    const float* w3 = (const float*)d_in[4];
    const float* w4 = (const float*)d_in[5];
    const float* w5 = (const float*)d_in[6];
    const float* w6 = (const float*)d_in[7];
    const float* w7 = (const float*)d_in[8];
    const float* w8 = (const float*)d_in[9];
    float* out = (float*)d_out;

    static bool attr_set = false;
    if (!attr_set) {
        cudaFuncSetAttribute(matching_kernel,
                             cudaFuncAttributeMaxDynamicSharedMemorySize,
                             SMEM_FLOATS * (int)sizeof(float));
        attr_set = true;
    }
    dim3 grid(256, 2, 2);
    matching_kernel<<<grid, NT, SMEM_FLOATS * sizeof(float)>>>(
        s1, s2, w1, w2, w3, w4, w5, w6, w7, w8, out);
}

// round 16
// speedup vs baseline: 1.6629x; 1.0463x over previous
#include <cuda_runtime.h>
#include <math.h>
#include <stdint.h>

#define EPSf 1e-6f
#define NT 256
#define STR 108   // float4-aligned row stride; conflict-free for frag + float4 patterns

// ---- shared memory layout (float offsets) — 25,094 floats = 100.4 KB ----
#define S1O   0        // s1R[ii*108+d]  local 50 rows (5400)
#define S2O   5400     // s2R[j*108+d]   104 rows (11232), rows 100..103 zero
#define CMO   16632    // cm[ii*108+j] (5400) — reused as att after phase 5
#define WMO   22032    // w_maxpool^2 [p*104+d] (1040), cols 100..103 zero
#define R1WO  23072    // 1/n1w [ii*10+p] (500)
#define R2WO  23572    // 1/n2w [j*10+p] (1000)
#define R1O   24572    // 1/||s1_ii|| (50)
#define R2O   24622    // 1/||s2_j|| (100)
#define RSO   24722    // rowsum per ii (50)
#define JMO   24772    // argmax j per ii (int) (50)
#define R2FO  24822    // full n2 per p (16)
#define MPO   24838    // maxpool scratch mp[64][2p][2nh] (256)
#define SMEM_FLOATS 25094

__device__ __forceinline__ float invs(float x) { return 1.0f / sqrtf(fmaxf(x, EPSf)); }

__device__ __forceinline__ float2 ffma2(float2 a, float2 b, float2 c) {
    unsigned long long ua = *reinterpret_cast<unsigned long long*>(&a);
    unsigned long long ub = *reinterpret_cast<unsigned long long*>(&b);
    unsigned long long uc = *reinterpret_cast<unsigned long long*>(&c);
    unsigned long long ud;
    asm("fma.rn.f32x2 %0, %1, %2, %3;" : "=l"(ud) : "l"(ua), "l"(ub), "l"(uc));
    return *reinterpret_cast<float2*>(&ud);
}
__device__ __forceinline__ float2 fmul2(float2 a, float2 b) {
    unsigned long long ua = *reinterpret_cast<unsigned long long*>(&a);
    unsigned long long ub = *reinterpret_cast<unsigned long long*>(&b);
    unsigned long long ud;
    asm("mul.rn.f32x2 %0, %1, %2;" : "=l"(ud) : "l"(ua), "l"(ub));
    return *reinterpret_cast<float2*>(&ud);
}

// tf32 conversion (round-to-nearest — unbiased) and Ampere-style mma.sync
__device__ __forceinline__ uint32_t cvt_tf32(float x) {
    uint32_t u;
    asm("cvt.rna.tf32.f32 %0, %1;" : "=r"(u) : "f"(x));
    return u;
}
__device__ __forceinline__ void mma_tf32(float* c,
    uint32_t a0, uint32_t a1, uint32_t a2, uint32_t a3,
    uint32_t b0, uint32_t b1) {
    asm volatile(
        "mma.sync.aligned.m16n8k8.row.col.f32.tf32.tf32.f32 "
        "{%0,%1,%2,%3}, {%4,%5,%6,%7}, {%8,%9}, {%0,%1,%2,%3};"
        : "+f"(c[0]), "+f"(c[1]), "+f"(c[2]), "+f"(c[3])
        : "r"(a0), "r"(a1), "r"(a2), "r"(a3), "r"(b0), "r"(b1));
}

__global__ __launch_bounds__(NT, 2) void matching_kernel(
    const float* __restrict__ s1g, const float* __restrict__ s2g,
    const float* __restrict__ w1, const float* __restrict__ w2,
    const float* __restrict__ w3, const float* __restrict__ w4,
    const float* __restrict__ w5, const float* __restrict__ w6,
    const float* __restrict__ w7, const float* __restrict__ w8,
    float* __restrict__ out)
{
    extern __shared__ float sm[];
    const int b   = blockIdx.x;        // batch 0..255
    const int dir = blockIdx.y;        // 0=fwd, 1=bwd
    const int ib  = blockIdx.z * 50;   // i half: global rows [ib, ib+50)
    const int tid = threadIdx.x;
    const int dOff = dir * 100;

    float* s1R = sm + S1O;
    float* s2R = sm + S2O;
    float* cm  = sm + CMO;             // cm during phases 2-5, att afterwards

    const float* wf = dir ? w2 : w1;
    const float* wm = dir ? w4 : w3;
    const float* we = dir ? w6 : w5;
    const float* ws = dir ? w8 : w7;

    // ================= phase 0: wm^2 (stride 104, zero pad) + slices ========
    for (int e = tid; e < 1000; e += NT) {
        float a = wm[e];
        sm[WMO + (e / 100) * 104 + (e % 100)] = a * a;
    }
    if (tid < 40) sm[WMO + (tid >> 2) * 104 + 100 + (tid & 3)] = 0.f;
    for (int e = tid; e < 5000; e += NT) {
        int ii = e / 100, d = e - ii * 100;
        s1R[ii * STR + d] = s1g[((size_t)(ib + ii) * 256 + b) * 200 + dOff + d];
    }
    for (int e = tid; e < 10000; e += NT) {
        int j = e / 100, d = e - j * 100;
        s2R[j * STR + d] = s2g[((size_t)j * 256 + b) * 200 + dOff + d];
    }
    // zero d-pad cols 100..107 (K padding for mma)
    for (int e = tid; e < 400; e += NT) s1R[(e >> 3) * STR + 100 + (e & 7)] = 0.f;
    for (int e = tid; e < 800; e += NT) s2R[(e >> 3) * STR + 100 + (e & 7)] = 0.f;
    // zero s2 pad rows 100..103 (K padding for phase-5 mma)
    for (int e = tid; e < 432; e += NT) s2R[100 * STR + e] = 0.f;
    __syncthreads();

    // ================= phase 1: norms (parallel sub-jobs) ===================
    if (tid < 50) {                          // 1/||s1_ii||
        float2 a = make_float2(0.f, 0.f);
        for (int d = 0; d < 100; d += 2) {
            float2 v = *(const float2*)&s1R[tid * STR + d];
            a = ffma2(v, v, a);
        }
        sm[R1O + tid] = invs(a.x + a.y);
    } else if (tid < 150) {                  // 1/||s2_j||
        int j = tid - 50;
        float2 a = make_float2(0.f, 0.f);
        for (int d = 0; d < 100; d += 2) {
            float2 v = *(const float2*)&s2R[j * STR + d];
            a = ffma2(v, v, a);
        }
        sm[R2O + j] = invs(a.x + a.y);
    } else if (tid < 160) {                  // full's n2 on s2[99] per p
        int p = tid - 150;
        float2 a = make_float2(0.f, 0.f);
        for (int d = 0; d < 100; d += 2) {
            float2 v = *(const float2*)&s2R[99 * STR + d];
            float2 w = __ldg((const float2*)&wf[p * 100 + d]);
            a = ffma2(fmul2(v, v), fmul2(w, w), a);
        }
        sm[R2FO + p] = invs(a.x + a.y);
    } else if (tid < 220) {                  // weighted norms as 5x5 tiles
        int t = tid - 160;                   // 0..59 : 0..19 s1 (50 rows), 20..59 s2
        int which = (t >= 20);
        int r = which ? (t - 20) : t;
        int i0 = (r / 2) * 5;
        int p0 = (r % 2) * 5;
        const float* base = which ? s2R : s1R;
        float2 acc[5][5];
        #pragma unroll
        for (int m = 0; m < 5; m++)
            #pragma unroll
            for (int q = 0; q < 5; q++) acc[m][q] = make_float2(0.f, 0.f);
        for (int d = 0; d < 100; d += 2) {
            float2 wv[5];
            #pragma unroll
            for (int q = 0; q < 5; q++)
                wv[q] = *(const float2*)&sm[WMO + (p0 + q) * 104 + d];
            #pragma unroll
            for (int m = 0; m < 5; m++) {
                float2 v = *(const float2*)&base[(i0 + m) * STR + d];
                float2 sq = fmul2(v, v);
                #pragma unroll
                for (int q = 0; q < 5; q++) acc[m][q] = ffma2(sq, wv[q], acc[m][q]);
            }
        }
        float* dst = sm + (which ? R2WO : R1WO);
        #pragma unroll
        for (int m = 0; m < 5; m++)
            #pragma unroll
            for (int q = 0; q < 5; q++)
                dst[(i0 + m) * 10 + p0 + q] = invs(acc[m][q].x + acc[m][q].y);
    }
    __syncthreads();

    // ====== phase 2: cosm GEMM (250 thr, 5x4 tile, float4 over d) ===========
    if (tid < 250) {
        const int ty = tid / 25;       // 0..9
        const int tx = tid - ty * 25;  // 0..24
        const int i0 = ty * 5;
        float2 acc[5][4];
        #pragma unroll
        for (int m = 0; m < 5; m++)
            #pragma unroll
            for (int n = 0; n < 4; n++) acc[m][n] = make_float2(0.f, 0.f);
        for (int d = 0; d < 100; d += 4) {
            float4 bv[4];
            #pragma unroll
            for (int n = 0; n < 4; n++)
                bv[n] = *(const float4*)&s2R[(tx + 25 * n) * STR + d];
            #pragma unroll
            for (int m = 0; m < 5; m++) {
                float4 a = *(const float4*)&s1R[(i0 + m) * STR + d];
                float2 alo = make_float2(a.x, a.y), ahi = make_float2(a.z, a.w);
                #pragma unroll
                for (int n = 0; n < 4; n++) {
                    acc[m][n] = ffma2(alo, make_float2(bv[n].x, bv[n].y), acc[m][n]);
                    acc[m][n] = ffma2(ahi, make_float2(bv[n].z, bv[n].w), acc[m][n]);
                }
            }
        }
        #pragma unroll
        for (int m = 0; m < 5; m++) {
            int ii = i0 + m;
            float r1 = sm[R1O + ii];
            #pragma unroll
            for (int n = 0; n < 4; n++) {
                int j = tx + 25 * n;
                cm[ii * STR + j] = (acc[m][n].x + acc[m][n].y) * r1 * sm[R2O + j];
            }
        }
    }
    // zero cm K-pad cols 100..103 (phase-5 mma)
    if (tid < 200) cm[(tid >> 2) * STR + 100 + (tid & 3)] = 0.f;
    __syncthreads();

    // ================= phase 3: rowsum + argmax (first-max, exact) ==========
    if (tid < 50) {
        float rs = 0.f, best = -1e30f; int bj = 0;
        for (int j = 0; j < 100; j++) {
            float v = cm[tid * STR + j];
            rs += v;
            if (v > best) { best = v; bj = j; }
        }
        sm[RSO + tid] = rs;
        reinterpret_cast<int*>(sm)[JMO + tid] = bj;
    }
    __syncthreads();

    // ====== phase 3.5: pre-round s2R and cm to tf32 in place ================
    for (int e = tid; e < 10800; e += NT)
        s2R[e] = __uint_as_float(cvt_tf32(s2R[e]));
    for (int e = tid; e < 5400; e += NT)
        cm[e] = __uint_as_float(cvt_tf32(cm[e]));
    __syncthreads();

    // ====== phase 4: maxpool via mma.sync tf32, p-PAIRED (B shared, no cvt) =
    {
        const int lane = tid & 31;
        const int wid8 = tid >> 5;         // 0..7
        const int mt = wid8 & 3;
        const int nh = wid8 >> 2;
        const int ntiles = nh ? 6 : 7;
        const int j0w = nh * 56;           // nh0: j 0..55 (7 tiles), nh1: 56..103 (6)
        const int g = lane >> 2, tc = lane & 3;
        const int arow0 = (mt * 16 + g) * STR;
        const int arow1 = arow0 + 8 * STR;
        float* mp = sm + MPO;              // [i(64)][p-in-pair(2)][nh(2)]
        const int i0g = mt * 16 + g;
        const int i1g = i0g + 8;
        for (int pp = 0; pp < 5; pp++) {
            const int pA = pp * 2, pB = pA + 1;
            float accA[7][4], accB[7][4];
            #pragma unroll
            for (int n = 0; n < 7; n++)
                #pragma unroll
                for (int q = 0; q < 4; q++) { accA[n][q] = 0.f; accB[n][q] = 0.f; }
            const float* wpA = sm + WMO + pA * 104;
            const float* wpB = wpA + 104;
            for (int k = 0; k < 13; k++) {
                int d0 = k * 8;
                float s00 = s1R[arow0 + d0 + tc],     s10 = s1R[arow1 + d0 + tc];
                float s01 = s1R[arow0 + d0 + tc + 4], s11 = s1R[arow1 + d0 + tc + 4];
                float wA0 = wpA[d0 + tc], wA1 = wpA[d0 + tc + 4];
                float wB0 = wpB[d0 + tc], wB1 = wpB[d0 + tc + 4];
                uint32_t aA0 = cvt_tf32(s00 * wA0), aA1 = cvt_tf32(s10 * wA0);
                uint32_t aA2 = cvt_tf32(s01 * wA1), aA3 = cvt_tf32(s11 * wA1);
                uint32_t aB0 = cvt_tf32(s00 * wB0), aB1 = cvt_tf32(s10 * wB0);
                uint32_t aB2 = cvt_tf32(s01 * wB1), aB3 = cvt_tf32(s11 * wB1);
                #pragma unroll
                for (int n = 0; n < 7; n++) {
                    if (n < ntiles) {
                        int jrow = (j0w + n * 8 + g) * STR;
                        uint32_t b0 = __float_as_uint(s2R[jrow + d0 + tc]);
                        uint32_t b1 = __float_as_uint(s2R[jrow + d0 + tc + 4]);
                        mma_tf32(accA[n], aA0, aA1, aA2, aA3, b0, b1);
                        mma_tf32(accB[n], aB0, aB1, aB2, aB3, b0, b1);
                    }
                }
            }
            // epilogue: scale by norms, mask pads, j-max in regs + shfl, both p
            float pmA0 = -1e30f, pmA1 = -1e30f, pmB0 = -1e30f, pmB1 = -1e30f;
            float r1aA = (i0g < 50) ? sm[R1WO + i0g * 10 + pA] : 0.f;
            float r1bA = (i1g < 50) ? sm[R1WO + i1g * 10 + pA] : 0.f;
            float r1aB = (i0g < 50) ? sm[R1WO + i0g * 10 + pB] : 0.f;
            float r1bB = (i1g < 50) ? sm[R1WO + i1g * 10 + pB] : 0.f;
            #pragma unroll
            for (int n = 0; n < 7; n++) {
                if (n < ntiles) {
                    int j = j0w + n * 8 + 2 * tc;
                    if (j < 100) {
                        float r2A = sm[R2WO + j * 10 + pA];
                        float r2B = sm[R2WO + j * 10 + pB];
                        pmA0 = fmaxf(pmA0, accA[n][0] * r1aA * r2A);
                        pmA1 = fmaxf(pmA1, accA[n][2] * r1bA * r2A);
                        pmB0 = fmaxf(pmB0, accB[n][0] * r1aB * r2B);
                        pmB1 = fmaxf(pmB1, accB[n][2] * r1bB * r2B);
                    }
                    if (j + 1 < 100) {
                        float r2A = sm[R2WO + (j + 1) * 10 + pA];
                        float r2B = sm[R2WO + (j + 1) * 10 + pB];
                        pmA0 = fmaxf(pmA0, accA[n][1] * r1aA * r2A);
                        pmA1 = fmaxf(pmA1, accA[n][3] * r1bA * r2A);
                        pmB0 = fmaxf(pmB0, accB[n][1] * r1aB * r2B);
                        pmB1 = fmaxf(pmB1, accB[n][3] * r1bB * r2B);
                    }
                }
            }
            pmA0 = fmaxf(pmA0, __shfl_xor_sync(0xffffffffu, pmA0, 1));
            pmA0 = fmaxf(pmA0, __shfl_xor_sync(0xffffffffu, pmA0, 2));
            pmA1 = fmaxf(pmA1, __shfl_xor_sync(0xffffffffu, pmA1, 1));
            pmA1 = fmaxf(pmA1, __shfl_xor_sync(0xffffffffu, pmA1, 2));
            pmB0 = fmaxf(pmB0, __shfl_xor_sync(0xffffffffu, pmB0, 1));
            pmB0 = fmaxf(pmB0, __shfl_xor_sync(0xffffffffu, pmB0, 2));
            pmB1 = fmaxf(pmB1, __shfl_xor_sync(0xffffffffu, pmB1, 1));
            pmB1 = fmaxf(pmB1, __shfl_xor_sync(0xffffffffu, pmB1, 2));
            if (tc == 0) {
                mp[i0g * 4 + 0 + nh] = pmA0;
                mp[i1g * 4 + 0 + nh] = pmA1;
                mp[i0g * 4 + 2 + nh] = pmB0;
                mp[i1g * 4 + 2 + nh] = pmB1;
            }
            __syncthreads();
            if (tid < 100) {
                int q = tid / 50, ii = tid - q * 50;   // q: 0->pA, 1->pB
                float mv = fmaxf(mp[ii * 4 + q * 2], mp[ii * 4 + q * 2 + 1]);
                out[((size_t)(ib + ii) * 256 + b) * 80 + 20 + dir * 10 + pA + q] = mv;
            }
            __syncthreads();
        }
    }

    // ====== phase 5: mean attention via mma.sync tf32 (no cvt at all) ======
    {
        const int lane = tid & 31;
        const int wid8 = tid >> 5;
        const int mt = wid8 & 3;
        const int nh = wid8 >> 2;
        const int ntiles = nh ? 6 : 7;
        const int dbase0 = nh * 56;
        const int g = lane >> 2, tc = lane & 3;
        const int arow0 = (mt * 16 + g) * STR;
        const int arow1 = arow0 + 8 * STR;
        const int i0g = mt * 16 + g;
        const int i1g = i0g + 8;
        float acc[7][4];
        #pragma unroll
        for (int n = 0; n < 7; n++)
            #pragma unroll
            for (int q = 0; q < 4; q++) acc[n][q] = 0.f;
        for (int k = 0; k < 13; k++) {
            int k0 = k * 8;
            uint32_t a0 = __float_as_uint(cm[arow0 + k0 + tc]);
            uint32_t a1 = __float_as_uint(cm[arow1 + k0 + tc]);
            uint32_t a2 = __float_as_uint(cm[arow0 + k0 + tc + 4]);
            uint32_t a3 = __float_as_uint(cm[arow1 + k0 + tc + 4]);
            #pragma unroll
            for (int n = 0; n < 7; n++) {
                if (n < ntiles) {
                    int dc = dbase0 + n * 8 + g;
                    uint32_t b0 = __float_as_uint(s2R[(k0 + tc) * STR + dc]);
                    uint32_t b1 = __float_as_uint(s2R[(k0 + tc + 4) * STR + dc]);
                    mma_tf32(acc[n], a0, a1, a2, a3, b0, b1);
                }
            }
        }
        __syncthreads();        // all cm reads complete before att overwrites it
        float rd0 = (i0g < 50) ? 1.0f / (sm[RSO + i0g] + EPSf) : 0.f;
        float rd1 = (i1g < 50) ? 1.0f / (sm[RSO + i1g] + EPSf) : 0.f;
        #pragma unroll
        for (int n = 0; n < 7; n++) {
            if (n < ntiles) {
                int d1 = dbase0 + n * 8 + 2 * tc;
                if (i0g < 50) {
                    if (d1 < 100)     cm[i0g * STR + d1]     = acc[n][0] * rd0;
                    if (d1 + 1 < 100) cm[i0g * STR + d1 + 1] = acc[n][1] * rd0;
                }
                if (i1g < 50) {
                    if (d1 < 100)     cm[i1g * STR + d1]     = acc[n][2] * rd1;
                    if (d1 + 1 < 100) cm[i1g * STR + d1 + 1] = acc[n][3] * rd1;
                }
            }
        }
    }
    __syncthreads();
    float* attS = cm;

    // ======== phase 6: features (f32x2 packed) — full, mean, (dir1) slot4 ===
    for (int r = 0; r < 2; r++) {
        int task = tid + NT * r;
        if (task < 500) {
            int ii = task / 10, p = task - ii * 10;
            const float* wfp = wf + p * 100;
            const float* wep = we + p * 100;
            const float* wsp = ws + p * 100;
            float2 numF = make_float2(0.f, 0.f), n1F = numF;
            float2 numE = numF, n1E = numF, n2E = numF;
            float2 numS = numF, n1S = numF, n2S = numF;
            for (int d = 0; d < 100; d += 2) {
                float2 v1  = *(const float2*)&s1R[ii * STR + d];
                float2 v2l = *(const float2*)&s2R[99 * STR + d];
                float2 av  = *(const float2*)&attS[ii * STR + d];
                float2 wfv = __ldg((const float2*)&wfp[d]);
                float2 wev = __ldg((const float2*)&wep[d]);
                float2 wf2 = fmul2(wfv, wfv);
                float2 we2 = fmul2(wev, wev);
                float2 t11 = fmul2(v1, v1);
                float2 t12 = fmul2(v1, v2l);
                float2 t1a = fmul2(v1, av);
                float2 taa = fmul2(av, av);
                numF = ffma2(t12, wf2, numF);
                n1F  = ffma2(t11, wf2, n1F);
                numE = ffma2(t1a, we2, numE);
                n1E  = ffma2(t11, we2, n1E);
                n2E  = ffma2(taa, we2, n2E);
                if (dir == 1) {
                    float2 wsv = __ldg((const float2*)&wsp[d]);
                    float2 ws2 = fmul2(wsv, wsv);
                    numS = ffma2(t1a, ws2, numS);
                    n1S  = ffma2(t11, ws2, n1S);
                    n2S  = ffma2(taa, ws2, n2S);
                }
            }
            size_t ob = ((size_t)(ib + ii) * 256 + b) * 80 + dir * 10 + p;
            out[ob +  0] = (numF.x + numF.y) * invs(n1F.x + n1F.y) * sm[R2FO + p];
            out[ob + 40] = (numE.x + numE.y) * invs(n1E.x + n1E.y) * invs(n2E.x + n2E.y);
            if (dir == 1)
                out[ob + 60] = (numS.x + numS.y) * invs(n1S.x + n1S.y) * invs(n2S.x + n2S.y);
        }
    }

    // ======== phase 7 (dir==0 only): max-att features (packed, ref bug) ====
    if (dir == 0) {
        for (int r = 0; r < 2; r++) {
            int task = tid + NT * r;
            if (task < 500) {
                int ii = task / 10, p = task - ii * 10;
                int jm = reinterpret_cast<int*>(sm)[JMO + ii];
                const float* av_row = s2g + (size_t)jm * 200;
                const float* wsp = ws + p * 100;
                float2 num = make_float2(0.f, 0.f), n1 = num, n2 = num;
                for (int d = 0; d < 100; d += 2) {
                    float2 v1 = *(const float2*)&s1R[ii * STR + d];
                    float2 av = __ldg((const float2*)&av_row[d]);
                    float2 wsv = __ldg((const float2*)&wsp[d]);
                    float2 ws2 = fmul2(wsv, wsv);
                    num = ffma2(fmul2(v1, av), ws2, num);
                    n1  = ffma2(fmul2(v1, v1), ws2, n1);
                    n2  = ffma2(fmul2(av, av), ws2, n2);
                }
                out[((size_t)(ib + ii) * 256 + b) * 80 + 60 + p] =
                    (num.x + num.y) * invs(n1.x + n1.y) * invs(n2.x + n2.y);
            }
        }
    }
}

extern "C" void kernel_launch(void* const* d_in, const int* in_sizes, int n_in,
                              void* d_out, int out_size) {
    const float* s1 = (const float*)d_in[0];
    const float* s2 = (const float*)d_in[1];
    const float* w1 = (const float*)d_in[2];
    const float* w2 = (const float*)d_in[3];
    const float* w3 = (const float*)d_in[4];
    const float* w4 = (const float*)d_in[5];
    const float* w5 = (const float*)d_in[6];
    const float* w6 = (const float*)d_in[7];
    const float* w7 = (const float*)d_in[8];
    const float* w8 = (const float*)d_in[9];
    float* out = (float*)d_out;

    static bool attr_set = false;
    if (!attr_set) {
        cudaFuncSetAttribute(matching_kernel,
                             cudaFuncAttributeMaxDynamicSharedMemorySize,
                             SMEM_FLOATS * (int)sizeof(float));
        attr_set = true;
    }
    dim3 grid(256, 2, 2);
    matching_kernel<<<grid, NT, SMEM_FLOATS * sizeof(float)>>>(
        s1, s2, w1, w2, w3, w4, w5, w6, w7, w8, out);
}

// round 17
// speedup vs baseline: 1.7108x; 1.0288x over previous
#include <cuda_runtime.h>
#include <math.h>
#include <stdint.h>

#define EPSf 1e-6f
#define NT 256
#define STR 108   // float4-aligned row stride; conflict-free for frag + float4 patterns

// ---- shared memory layout (float offsets) — 26,118 floats = 104.5 KB ----
#define S1O   0        // s1R[ii*108+d]  local 50 rows (5400)
#define S2O   5400     // s2R[j*108+d]   104 rows (11232), rows 100..103 zero
#define CMO   16632    // cm[ii*108+j] (5400) — reused as att after phase 5
#define WMO   22032    // w_maxpool^2 [p*104+d] (1040), cols 100..103 zero
#define R1WO  23072    // 1/n1w [ii*10+p] (500)
#define R2WO  23572    // 1/n2w [j*10+p] (1000)
#define R1O   24572    // 1/||s1_ii|| (50)
#define R2O   24622    // 1/||s2_j|| (100)
#define RSO   24722    // rowsum per ii (50)
#define JMO   24772    // argmax j per ii (int) (50)
#define R2FO  24822    // full n2 per p (16)
#define MPO   24838    // maxpool scratch mp[i(64)][p(10)][nh(2)] (1280)
#define SMEM_FLOATS 26118

__device__ __forceinline__ float invs(float x) { return 1.0f / sqrtf(fmaxf(x, EPSf)); }

__device__ __forceinline__ float2 ffma2(float2 a, float2 b, float2 c) {
    unsigned long long ua = *reinterpret_cast<unsigned long long*>(&a);
    unsigned long long ub = *reinterpret_cast<unsigned long long*>(&b);
    unsigned long long uc = *reinterpret_cast<unsigned long long*>(&c);
    unsigned long long ud;
    asm("fma.rn.f32x2 %0, %1, %2, %3;" : "=l"(ud) : "l"(ua), "l"(ub), "l"(uc));
    return *reinterpret_cast<float2*>(&ud);
}
__device__ __forceinline__ float2 fmul2(float2 a, float2 b) {
    unsigned long long ua = *reinterpret_cast<unsigned long long*>(&a);
    unsigned long long ub = *reinterpret_cast<unsigned long long*>(&b);
    unsigned long long ud;
    asm("mul.rn.f32x2 %0, %1, %2;" : "=l"(ud) : "l"(ua), "l"(ub));
    return *reinterpret_cast<float2*>(&ud);
}

// tf32 conversion (round-to-nearest — unbiased) and Ampere-style mma.sync
__device__ __forceinline__ uint32_t cvt_tf32(float x) {
    uint32_t u;
    asm("cvt.rna.tf32.f32 %0, %1;" : "=r"(u) : "f"(x));
    return u;
}
__device__ __forceinline__ void mma_tf32(float* c,
    uint32_t a0, uint32_t a1, uint32_t a2, uint32_t a3,
    uint32_t b0, uint32_t b1) {
    asm volatile(
        "mma.sync.aligned.m16n8k8.row.col.f32.tf32.tf32.f32 "
        "{%0,%1,%2,%3}, {%4,%5,%6,%7}, {%8,%9}, {%0,%1,%2,%3};"
        : "+f"(c[0]), "+f"(c[1]), "+f"(c[2]), "+f"(c[3])
        : "r"(a0), "r"(a1), "r"(a2), "r"(a3), "r"(b0), "r"(b1));
}

__global__ __launch_bounds__(NT, 2) void matching_kernel(
    const float* __restrict__ s1g, const float* __restrict__ s2g,
    const float* __restrict__ w1, const float* __restrict__ w2,
    const float* __restrict__ w3, const float* __restrict__ w4,
    const float* __restrict__ w5, const float* __restrict__ w6,
    const float* __restrict__ w7, const float* __restrict__ w8,
    float* __restrict__ out)
{
    extern __shared__ float sm[];
    const int b   = blockIdx.x;        // batch 0..255
    const int dir = blockIdx.y;        // 0=fwd, 1=bwd
    const int ib  = blockIdx.z * 50;   // i half: global rows [ib, ib+50)
    const int tid = threadIdx.x;
    const int dOff = dir * 100;

    float* s1R = sm + S1O;
    float* s2R = sm + S2O;
    float* cm  = sm + CMO;             // cm during phases 2-5, att afterwards

    const float* wf = dir ? w2 : w1;
    const float* wm = dir ? w4 : w3;
    const float* we = dir ? w6 : w5;
    const float* ws = dir ? w8 : w7;

    // ================= phase 0: wm^2 (stride 104, zero pad) + slices ========
    for (int e = tid; e < 1000; e += NT) {
        float a = wm[e];
        sm[WMO + (e / 100) * 104 + (e % 100)] = a * a;
    }
    if (tid < 40) sm[WMO + (tid >> 2) * 104 + 100 + (tid & 3)] = 0.f;
    for (int e = tid; e < 5000; e += NT) {
        int ii = e / 100, d = e - ii * 100;
        s1R[ii * STR + d] = s1g[((size_t)(ib + ii) * 256 + b) * 200 + dOff + d];
    }
    for (int e = tid; e < 10000; e += NT) {
        int j = e / 100, d = e - j * 100;
        s2R[j * STR + d] = s2g[((size_t)j * 256 + b) * 200 + dOff + d];
    }
    // zero d-pad cols 100..107 (K padding for mma)
    for (int e = tid; e < 400; e += NT) s1R[(e >> 3) * STR + 100 + (e & 7)] = 0.f;
    for (int e = tid; e < 800; e += NT) s2R[(e >> 3) * STR + 100 + (e & 7)] = 0.f;
    // zero s2 pad rows 100..103 (K padding for phase-5 mma)
    for (int e = tid; e < 432; e += NT) s2R[100 * STR + e] = 0.f;
    __syncthreads();

    // ================= phase 1: norms (parallel sub-jobs) ===================
    if (tid < 50) {                          // 1/||s1_ii||
        float2 a = make_float2(0.f, 0.f);
        for (int d = 0; d < 100; d += 2) {
            float2 v = *(const float2*)&s1R[tid * STR + d];
            a = ffma2(v, v, a);
        }
        sm[R1O + tid] = invs(a.x + a.y);
    } else if (tid < 150) {                  // 1/||s2_j||
        int j = tid - 50;
        float2 a = make_float2(0.f, 0.f);
        for (int d = 0; d < 100; d += 2) {
            float2 v = *(const float2*)&s2R[j * STR + d];
            a = ffma2(v, v, a);
        }
        sm[R2O + j] = invs(a.x + a.y);
    } else if (tid < 160) {                  // full's n2 on s2[99] per p
        int p = tid - 150;
        float2 a = make_float2(0.f, 0.f);
        for (int d = 0; d < 100; d += 2) {
            float2 v = *(const float2*)&s2R[99 * STR + d];
            float2 w = __ldg((const float2*)&wf[p * 100 + d]);
            a = ffma2(fmul2(v, v), fmul2(w, w), a);
        }
        sm[R2FO + p] = invs(a.x + a.y);
    } else if (tid < 220) {                  // weighted norms as 5x5 tiles
        int t = tid - 160;                   // 0..59 : 0..19 s1 (50 rows), 20..59 s2
        int which = (t >= 20);
        int r = which ? (t - 20) : t;
        int i0 = (r / 2) * 5;
        int p0 = (r % 2) * 5;
        const float* base = which ? s2R : s1R;
        float2 acc[5][5];
        #pragma unroll
        for (int m = 0; m < 5; m++)
            #pragma unroll
            for (int q = 0; q < 5; q++) acc[m][q] = make_float2(0.f, 0.f);
        for (int d = 0; d < 100; d += 2) {
            float2 wv[5];
            #pragma unroll
            for (int q = 0; q < 5; q++)
                wv[q] = *(const float2*)&sm[WMO + (p0 + q) * 104 + d];
            #pragma unroll
            for (int m = 0; m < 5; m++) {
                float2 v = *(const float2*)&base[(i0 + m) * STR + d];
                float2 sq = fmul2(v, v);
                #pragma unroll
                for (int q = 0; q < 5; q++) acc[m][q] = ffma2(sq, wv[q], acc[m][q]);
            }
        }
        float* dst = sm + (which ? R2WO : R1WO);
        #pragma unroll
        for (int m = 0; m < 5; m++)
            #pragma unroll
            for (int q = 0; q < 5; q++)
                dst[(i0 + m) * 10 + p0 + q] = invs(acc[m][q].x + acc[m][q].y);
    }
    __syncthreads();

    // ====== phase 2: cosm GEMM (250 thr, 5x4 tile, float4 over d) ===========
    if (tid < 250) {
        const int ty = tid / 25;       // 0..9
        const int tx = tid - ty * 25;  // 0..24
        const int i0 = ty * 5;
        float2 acc[5][4];
        #pragma unroll
        for (int m = 0; m < 5; m++)
            #pragma unroll
            for (int n = 0; n < 4; n++) acc[m][n] = make_float2(0.f, 0.f);
        for (int d = 0; d < 100; d += 4) {
            float4 bv[4];
            #pragma unroll
            for (int n = 0; n < 4; n++)
                bv[n] = *(const float4*)&s2R[(tx + 25 * n) * STR + d];
            #pragma unroll
            for (int m = 0; m < 5; m++) {
                float4 a = *(const float4*)&s1R[(i0 + m) * STR + d];
                float2 alo = make_float2(a.x, a.y), ahi = make_float2(a.z, a.w);
                #pragma unroll
                for (int n = 0; n < 4; n++) {
                    acc[m][n] = ffma2(alo, make_float2(bv[n].x, bv[n].y), acc[m][n]);
                    acc[m][n] = ffma2(ahi, make_float2(bv[n].z, bv[n].w), acc[m][n]);
                }
            }
        }
        #pragma unroll
        for (int m = 0; m < 5; m++) {
            int ii = i0 + m;
            float r1 = sm[R1O + ii];
            #pragma unroll
            for (int n = 0; n < 4; n++) {
                int j = tx + 25 * n;
                cm[ii * STR + j] = (acc[m][n].x + acc[m][n].y) * r1 * sm[R2O + j];
            }
        }
    }
    // zero cm K-pad cols 100..103 (phase-5 mma)
    if (tid < 200) cm[(tid >> 2) * STR + 100 + (tid & 3)] = 0.f;
    __syncthreads();

    // ================= phase 3: rowsum + argmax (first-max, exact) ==========
    if (tid < 50) {
        float rs = 0.f, best = -1e30f; int bj = 0;
        for (int j = 0; j < 100; j++) {
            float v = cm[tid * STR + j];
            rs += v;
            if (v > best) { best = v; bj = j; }
        }
        sm[RSO + tid] = rs;
        reinterpret_cast<int*>(sm)[JMO + tid] = bj;
    }
    __syncthreads();

    // ====== phase 3.5: pre-round s2R and cm to tf32 in place (float2) ======
    for (int e = tid; e < 5400; e += NT) {
        float2 v = *(const float2*)&s2R[e * 2];
        v.x = __uint_as_float(cvt_tf32(v.x));
        v.y = __uint_as_float(cvt_tf32(v.y));
        *(float2*)&s2R[e * 2] = v;
    }
    for (int e = tid; e < 2700; e += NT) {
        float2 v = *(const float2*)&cm[e * 2];
        v.x = __uint_as_float(cvt_tf32(v.x));
        v.y = __uint_as_float(cvt_tf32(v.y));
        *(float2*)&cm[e * 2] = v;
    }
    __syncthreads();

    // ====== phase 4: maxpool via mma.sync tf32, p-PAIRED, ONE barrier =======
    {
        const int lane = tid & 31;
        const int wid8 = tid >> 5;         // 0..7
        const int mt = wid8 & 3;
        const int nh = wid8 >> 2;
        const int ntiles = nh ? 6 : 7;
        const int j0w = nh * 56;           // nh0: j 0..55 (7 tiles), nh1: 56..103 (6)
        const int g = lane >> 2, tc = lane & 3;
        const int arow0 = (mt * 16 + g) * STR;
        const int arow1 = arow0 + 8 * STR;
        float* mp = sm + MPO;              // [i(64)][p(10)][nh(2)]
        const int i0g = mt * 16 + g;
        const int i1g = i0g + 8;
        for (int pp = 0; pp < 5; pp++) {
            const int pA = pp * 2, pB = pA + 1;
            float accA[7][4], accB[7][4];
            #pragma unroll
            for (int n = 0; n < 7; n++)
                #pragma unroll
                for (int q = 0; q < 4; q++) { accA[n][q] = 0.f; accB[n][q] = 0.f; }
            const float* wpA = sm + WMO + pA * 104;
            const float* wpB = wpA + 104;
            for (int k = 0; k < 13; k++) {
                int d0 = k * 8;
                float s00 = s1R[arow0 + d0 + tc],     s10 = s1R[arow1 + d0 + tc];
                float s01 = s1R[arow0 + d0 + tc + 4], s11 = s1R[arow1 + d0 + tc + 4];
                float wA0 = wpA[d0 + tc], wA1 = wpA[d0 + tc + 4];
                float wB0 = wpB[d0 + tc], wB1 = wpB[d0 + tc + 4];
                uint32_t aA0 = cvt_tf32(s00 * wA0), aA1 = cvt_tf32(s10 * wA0);
                uint32_t aA2 = cvt_tf32(s01 * wA1), aA3 = cvt_tf32(s11 * wA1);
                uint32_t aB0 = cvt_tf32(s00 * wB0), aB1 = cvt_tf32(s10 * wB0);
                uint32_t aB2 = cvt_tf32(s01 * wB1), aB3 = cvt_tf32(s11 * wB1);
                #pragma unroll
                for (int n = 0; n < 7; n++) {
                    if (n < ntiles) {
                        int jrow = (j0w + n * 8 + g) * STR;
                        uint32_t b0 = __float_as_uint(s2R[jrow + d0 + tc]);
                        uint32_t b1 = __float_as_uint(s2R[jrow + d0 + tc + 4]);
                        mma_tf32(accA[n], aA0, aA1, aA2, aA3, b0, b1);
                        mma_tf32(accB[n], aB0, aB1, aB2, aB3, b0, b1);
                    }
                }
            }
            // epilogue: scale by norms, mask pads, j-max in regs + shfl, both p
            float pmA0 = -1e30f, pmA1 = -1e30f, pmB0 = -1e30f, pmB1 = -1e30f;
            float r1aA = (i0g < 50) ? sm[R1WO + i0g * 10 + pA] : 0.f;
            float r1bA = (i1g < 50) ? sm[R1WO + i1g * 10 + pA] : 0.f;
            float r1aB = (i0g < 50) ? sm[R1WO + i0g * 10 + pB] : 0.f;
            float r1bB = (i1g < 50) ? sm[R1WO + i1g * 10 + pB] : 0.f;
            #pragma unroll
            for (int n = 0; n < 7; n++) {
                if (n < ntiles) {
                    int j = j0w + n * 8 + 2 * tc;
                    if (j < 100) {
                        float r2A = sm[R2WO + j * 10 + pA];
                        float r2B = sm[R2WO + j * 10 + pB];
                        pmA0 = fmaxf(pmA0, accA[n][0] * r1aA * r2A);
                        pmA1 = fmaxf(pmA1, accA[n][2] * r1bA * r2A);
                        pmB0 = fmaxf(pmB0, accB[n][0] * r1aB * r2B);
                        pmB1 = fmaxf(pmB1, accB[n][2] * r1bB * r2B);
                    }
                    if (j + 1 < 100) {
                        float r2A = sm[R2WO + (j + 1) * 10 + pA];
                        float r2B = sm[R2WO + (j + 1) * 10 + pB];
                        pmA0 = fmaxf(pmA0, accA[n][1] * r1aA * r2A);
                        pmA1 = fmaxf(pmA1, accA[n][3] * r1bA * r2A);
                        pmB0 = fmaxf(pmB0, accB[n][1] * r1aB * r2B);
                        pmB1 = fmaxf(pmB1, accB[n][3] * r1bB * r2B);
                    }
                }
            }
            pmA0 = fmaxf(pmA0, __shfl_xor_sync(0xffffffffu, pmA0, 1));
            pmA0 = fmaxf(pmA0, __shfl_xor_sync(0xffffffffu, pmA0, 2));
            pmA1 = fmaxf(pmA1, __shfl_xor_sync(0xffffffffu, pmA1, 1));
            pmA1 = fmaxf(pmA1, __shfl_xor_sync(0xffffffffu, pmA1, 2));
            pmB0 = fmaxf(pmB0, __shfl_xor_sync(0xffffffffu, pmB0, 1));
            pmB0 = fmaxf(pmB0, __shfl_xor_sync(0xffffffffu, pmB0, 2));
            pmB1 = fmaxf(pmB1, __shfl_xor_sync(0xffffffffu, pmB1, 1));
            pmB1 = fmaxf(pmB1, __shfl_xor_sync(0xffffffffu, pmB1, 2));
            if (tc == 0) {
                mp[i0g * 20 + pA * 2 + nh] = pmA0;
                mp[i1g * 20 + pA * 2 + nh] = pmA1;
                mp[i0g * 20 + pB * 2 + nh] = pmB0;
                mp[i1g * 20 + pB * 2 + nh] = pmB1;
            }
        }
        __syncthreads();                   // single barrier for all 10 p
        for (int r = 0; r < 2; r++) {
            int task = tid + NT * r;
            if (task < 500) {
                int ii = task / 10, p = task - ii * 10;
                float mv = fmaxf(mp[ii * 20 + p * 2], mp[ii * 20 + p * 2 + 1]);
                out[((size_t)(ib + ii) * 256 + b) * 80 + 20 + dir * 10 + p] = mv;
            }
        }
    }

    // ====== phase 5: mean attention via mma.sync tf32 (no cvt at all) ======
    {
        const int lane = tid & 31;
        const int wid8 = tid >> 5;
        const int mt = wid8 & 3;
        const int nh = wid8 >> 2;
        const int ntiles = nh ? 6 : 7;
        const int dbase0 = nh * 56;
        const int g = lane >> 2, tc = lane & 3;
        const int arow0 = (mt * 16 + g) * STR;
        const int arow1 = arow0 + 8 * STR;
        const int i0g = mt * 16 + g;
        const int i1g = i0g + 8;
        float acc[7][4];
        #pragma unroll
        for (int n = 0; n < 7; n++)
            #pragma unroll
            for (int q = 0; q < 4; q++) acc[n][q] = 0.f;
        for (int k = 0; k < 13; k++) {
            int k0 = k * 8;
            uint32_t a0 = __float_as_uint(cm[arow0 + k0 + tc]);
            uint32_t a1 = __float_as_uint(cm[arow1 + k0 + tc]);
            uint32_t a2 = __float_as_uint(cm[arow0 + k0 + tc + 4]);
            uint32_t a3 = __float_as_uint(cm[arow1 + k0 + tc + 4]);
            #pragma unroll
            for (int n = 0; n < 7; n++) {
                if (n < ntiles) {
                    int dc = dbase0 + n * 8 + g;
                    uint32_t b0 = __float_as_uint(s2R[(k0 + tc) * STR + dc]);
                    uint32_t b1 = __float_as_uint(s2R[(k0 + tc + 4) * STR + dc]);
                    mma_tf32(acc[n], a0, a1, a2, a3, b0, b1);
                }
            }
        }
        __syncthreads();        // all cm reads complete before att overwrites it
        float rd0 = (i0g < 50) ? 1.0f / (sm[RSO + i0g] + EPSf) : 0.f;
        float rd1 = (i1g < 50) ? 1.0f / (sm[RSO + i1g] + EPSf) : 0.f;
        #pragma unroll
        for (int n = 0; n < 7; n++) {
            if (n < ntiles) {
                int d1 = dbase0 + n * 8 + 2 * tc;
                if (i0g < 50) {
                    if (d1 < 100)     cm[i0g * STR + d1]     = acc[n][0] * rd0;
                    if (d1 + 1 < 100) cm[i0g * STR + d1 + 1] = acc[n][1] * rd0;
                }
                if (i1g < 50) {
                    if (d1 < 100)     cm[i1g * STR + d1]     = acc[n][2] * rd1;
                    if (d1 + 1 < 100) cm[i1g * STR + d1 + 1] = acc[n][3] * rd1;
                }
            }
        }
    }
    __syncthreads();
    float* attS = cm;

    // ======== phase 6: features (f32x2 packed) — full, mean, (dir1) slot4 ===
    for (int r = 0; r < 2; r++) {
        int task = tid + NT * r;
        if (task < 500) {
            int ii = task / 10, p = task - ii * 10;
            const float* wfp = wf + p * 100;
            const float* wep = we + p * 100;
            const float* wsp = ws + p * 100;
            float2 numF = make_float2(0.f, 0.f), n1F = numF;
            float2 numE = numF, n1E = numF, n2E = numF;
            float2 numS = numF, n1S = numF, n2S = numF;
            for (int d = 0; d < 100; d += 2) {
                float2 v1  = *(const float2*)&s1R[ii * STR + d];
                float2 v2l = *(const float2*)&s2R[99 * STR + d];
                float2 av  = *(const float2*)&attS[ii * STR + d];
                float2 wfv = __ldg((const float2*)&wfp[d]);
                float2 wev = __ldg((const float2*)&wep[d]);
                float2 wf2 = fmul2(wfv, wfv);
                float2 we2 = fmul2(wev, wev);
                float2 t11 = fmul2(v1, v1);
                float2 t12 = fmul2(v1, v2l);
                float2 t1a = fmul2(v1, av);
                float2 taa = fmul2(av, av);
                numF = ffma2(t12, wf2, numF);
                n1F  = ffma2(t11, wf2, n1F);
                numE = ffma2(t1a, we2, numE);
                n1E  = ffma2(t11, we2, n1E);
                n2E  = ffma2(taa, we2, n2E);
                if (dir == 1) {
                    float2 wsv = __ldg((const float2*)&wsp[d]);
                    float2 ws2 = fmul2(wsv, wsv);
                    numS = ffma2(t1a, ws2, numS);
                    n1S  = ffma2(t11, ws2, n1S);
                    n2S  = ffma2(taa, ws2, n2S);
                }
            }
            size_t ob = ((size_t)(ib + ii) * 256 + b) * 80 + dir * 10 + p;
            out[ob +  0] = (numF.x + numF.y) * invs(n1F.x + n1F.y) * sm[R2FO + p];
            out[ob + 40] = (numE.x + numE.y) * invs(n1E.x + n1E.y) * invs(n2E.x + n2E.y);
            if (dir == 1)
                out[ob + 60] = (numS.x + numS.y) * invs(n1S.x + n1S.y) * invs(n2S.x + n2S.y);
        }
    }

    // ======== phase 7 (dir==0 only): max-att features (packed, ref bug) ====
    if (dir == 0) {
        for (int r = 0; r < 2; r++) {
            int task = tid + NT * r;
            if (task < 500) {
                int ii = task / 10, p = task - ii * 10;
                int jm = reinterpret_cast<int*>(sm)[JMO + ii];
                const float* av_row = s2g + (size_t)jm * 200;
                const float* wsp = ws + p * 100;
                float2 num = make_float2(0.f, 0.f), n1 = num, n2 = num;
                for (int d = 0; d < 100; d += 2) {
                    float2 v1 = *(const float2*)&s1R[ii * STR + d];
                    float2 av = __ldg((const float2*)&av_row[d]);
                    float2 wsv = __ldg((const float2*)&wsp[d]);
                    float2 ws2 = fmul2(wsv, wsv);
                    num = ffma2(fmul2(v1, av), ws2, num);
                    n1  = ffma2(fmul2(v1, v1), ws2, n1);
                    n2  = ffma2(fmul2(av, av), ws2, n2);
                }
                out[((size_t)(ib + ii) * 256 + b) * 80 + 60 + p] =
                    (num.x + num.y) * invs(n1.x + n1.y) * invs(n2.x + n2.y);
            }
        }
    }
}

extern "C" void kernel_launch(void* const* d_in, const int* in_sizes, int n_in,
                              void* d_out, int out_size) {
    const float* s1 = (const float*)d_in[0];
    const float* s2 = (const float*)d_in[1];
    const float* w1 = (const float*)d_in[2];
    const float* w2 = (const float*)d_in[3];
    const float* w3 = (const float*)d_in[4];
    const float* w4 = (const float*)d_in[5];
    const float* w5 = (const float*)d_in[6];
    const float* w6 = (const float*)d_in[7];
    const float* w7 = (const float*)d_in[8];
    const float* w8 = (const float*)d_in[9];
    float* out = (float*)d_out;

    static bool attr_set = false;
    if (!attr_set) {
        cudaFuncSetAttribute(matching_kernel,
                             cudaFuncAttributeMaxDynamicSharedMemorySize,
                             SMEM_FLOATS * (int)sizeof(float));
        attr_set = true;
    }
    dim3 grid(256, 2, 2);
    matching_kernel<<<grid, NT, SMEM_FLOATS * sizeof(float)>>>(
        s1, s2, w1, w2, w3, w4, w5, w6, w7, w8, out);
}